// round 3
// baseline (speedup 1.0000x reference)
#include <cuda_runtime.h>
#include <cstdint>

#define BATCH 16
#define HIN 32
#define WIN 32
#define CH 512
#define HOUT 64
#define WOUT 64

typedef unsigned long long ull;

// ---------------- device scratch (allocation-free rule: static globals) ---------
__device__ float g_s1[BATCH][CH];
__device__ float g_s2[BATCH][CH];
__device__ float g_sr[BATCH][CH];
__device__ float g_d1[BATCH][CH];
__device__ float g_d2[BATCH][CH];
__device__ float g_wsq1[CH * CH];
__device__ float g_wsq2[CH * CH];
__device__ float g_y[(size_t)BATCH * HOUT * WOUT * CH];   // convT output, pre-blur
__device__ float g_x1[(size_t)BATCH * HOUT * WOUT * CH];  // style block 1 output

__device__ __forceinline__ float lrelu(float v) { return v > 0.f ? v : 0.2f * v; }

// pack a scalar into both halves of an f32x2 register pair
__device__ __forceinline__ ull pk(float x) {
    ull r;
    asm("mov.b64 %0, {%1, %1};" : "=l"(r) : "f"(x));
    return r;
}
// packed fp32 FMA (FFMA2) — 2 MACs/lane/instr, PTX-only on sm_103a
__device__ __forceinline__ void ffma2(ull& d, ull a, ull b) {
    asm("fma.rn.f32x2 %0, %1, %2, %0;" : "+l"(d) : "l"(a), "l"(b));
}

union F4U {
    float4 f;
    ull u[2];
    float s[4];
};

// ---------------- styles: s = w @ (fw/sqrt(512)) + fb --------------------------
__global__ void k_styles(const float* __restrict__ w, const float* __restrict__ fw,
                         const float* __restrict__ fb, int which) {
    int b = blockIdx.x, co = threadIdx.x;
    __shared__ float sw_[CH];
    sw_[co] = w[b * CH + co];
    __syncthreads();
    float acc = 0.f;
#pragma unroll 4
    for (int ci = 0; ci < CH; ci++) acc = fmaf(sw_[ci], fw[ci * CH + co], acc);
    float v = acc * 0.044194173824159216f + fb[co];  // 1/sqrt(512)
    if (which == 0) g_s1[b][co] = v;
    else if (which == 1) g_s2[b][co] = v;
    else g_sr[b][co] = v;
}

// ---------------- per-(ci,co) squared-weight sums for demod --------------------
__global__ void k_wsq(const float* __restrict__ w1, const float* __restrict__ w2) {
    int idx = blockIdx.x * 256 + threadIdx.x;  // < CH*CH
    const float ws2 = 1.0f / 4608.0f;          // wscale^2 = 1/(9*512)
    float a1 = 0.f, a2 = 0.f;
#pragma unroll
    for (int t = 0; t < 9; t++) {
        float v1 = w1[(size_t)t * CH * CH + idx];
        a1 = fmaf(v1, v1, a1);
        float v2 = w2[(size_t)t * CH * CH + idx];
        a2 = fmaf(v2, v2, a2);
    }
    g_wsq1[idx] = a1 * ws2;
    g_wsq2[idx] = a2 * ws2;
}

// ---------------- demod: d[b,co] = rsqrt(sum_ci s^2 * wsq + 1e-8) --------------
__global__ void k_demod(int which) {
    int b = blockIdx.x, co = threadIdx.x;
    __shared__ float ss[CH];
    float s = which ? g_s2[b][co] : g_s1[b][co];
    ss[co] = s * s;
    __syncthreads();
    const float* wsq = which ? g_wsq2 : g_wsq1;
    float acc = 0.f;
#pragma unroll 4
    for (int ci = 0; ci < CH; ci++) acc = fmaf(ss[ci], wsq[ci * CH + co], acc);
    float d = rsqrtf(acc + 1e-8f);
    if (which) g_d2[b][co] = d;
    else g_d1[b][co] = d;
}

// ---------------- conv_transpose 3x3 stride 2 (parity-decomposed) --------------
// y[p,q,co] = sum over dilated-input taps; p even: dh in {0,2}; p odd: dh=1.
// Per 2x2 output quad at (2i,2j): needs input (i-1..i, j-1..j).
__global__ __launch_bounds__(256) void k_convT(const float* __restrict__ x,
                                               const float* __restrict__ cw) {
    __shared__ __align__(16) float sw_[9][16][64];
    __shared__ float sx[16][25];
    int tid = threadIdx.x;
    int coq = tid & 15, pxq = tid >> 4;
    int qu = pxq >> 2, qv = pxq & 3;
    int co0 = blockIdx.x * 64;
    int tp = blockIdx.y >> 3, tq = blockIdx.y & 7;
    int b = blockIdx.z;
    int p0 = tp * 8, q0 = tq * 8;
    int i0 = (p0 >> 1) - 1, j0 = (q0 >> 1) - 1;
    const float wscale = 0.014731391274719742f;  // 1/sqrt(9*512)

    ull acc[4][2];
#pragma unroll
    for (int i = 0; i < 4; i++) { acc[i][0] = 0ull; acc[i][1] = 0ull; }

    for (int c0 = 0; c0 < CH; c0 += 16) {
        __syncthreads();
#pragma unroll
        for (int k = 0; k < 36; k++) {  // 9*16*64 = 36*256
            int idx = tid + k * 256;
            int co = idx & 63, ci = (idx >> 6) & 15, tap = idx >> 10;
            sw_[tap][ci][co] = cw[((size_t)tap * CH + c0 + ci) * CH + co0 + co] * wscale;
        }
        for (int idx = tid; idx < 25 * 16; idx += 256) {
            int ci = idx & 15, pos = idx >> 4;
            int r = pos / 5, cc = pos - r * 5;
            int gi = i0 + r, gj = j0 + cc;
            float v = 0.f;
            if ((unsigned)gi < HIN && (unsigned)gj < WIN)
                v = x[(((size_t)b * HIN + gi) * WIN + gj) * CH + c0 + ci] * g_s1[b][c0 + ci];
            sx[ci][pos] = v;
        }
        __syncthreads();
#pragma unroll 4
        for (int ci = 0; ci < 16; ci++) {
            float x00 = sx[ci][qu * 5 + qv],       x01 = sx[ci][qu * 5 + qv + 1];
            float x10 = sx[ci][(qu + 1) * 5 + qv], x11 = sx[ci][(qu + 1) * 5 + qv + 1];
            ull X00 = pk(x00), X01 = pk(x01), X10 = pk(x10), X11 = pk(x11);
            F4U wt[9];
#pragma unroll
            for (int t = 0; t < 9; t++) wt[t].f = *(const float4*)&sw_[t][ci][coq << 2];
            // ee (p even, q even): taps (0,0),(0,2),(2,0),(2,2)
            ffma2(acc[0][0], X00, wt[0].u[0]); ffma2(acc[0][1], X00, wt[0].u[1]);
            ffma2(acc[0][0], X01, wt[2].u[0]); ffma2(acc[0][1], X01, wt[2].u[1]);
            ffma2(acc[0][0], X10, wt[6].u[0]); ffma2(acc[0][1], X10, wt[6].u[1]);
            ffma2(acc[0][0], X11, wt[8].u[0]); ffma2(acc[0][1], X11, wt[8].u[1]);
            // eo: taps (0,1),(2,1)
            ffma2(acc[1][0], X01, wt[1].u[0]); ffma2(acc[1][1], X01, wt[1].u[1]);
            ffma2(acc[1][0], X11, wt[7].u[0]); ffma2(acc[1][1], X11, wt[7].u[1]);
            // oe: taps (1,0),(1,2)
            ffma2(acc[2][0], X10, wt[3].u[0]); ffma2(acc[2][1], X10, wt[3].u[1]);
            ffma2(acc[2][0], X11, wt[5].u[0]); ffma2(acc[2][1], X11, wt[5].u[1]);
            // oo: tap (1,1)
            ffma2(acc[3][0], X11, wt[4].u[0]); ffma2(acc[3][1], X11, wt[4].u[1]);
        }
    }
#pragma unroll
    for (int u = 0; u < 2; u++)
#pragma unroll
        for (int v = 0; v < 2; v++) {
            F4U o;
            o.u[0] = acc[u * 2 + v][0];
            o.u[1] = acc[u * 2 + v][1];
            int p = p0 + 2 * qu + u, q = q0 + 2 * qv + v;
            *(float4*)&g_y[(((size_t)b * HOUT + p) * WOUT + q) * CH + co0 + (coq << 2)] = o.f;
        }
}

// ---------------- blur (4x4 FIR, pad lo=1 hi=2) + demod + noise + bias + lrelu --
__global__ void k_blur(const float* __restrict__ noise1, const float* __restrict__ sn1,
                       const float* __restrict__ bias1) {
    int q = blockIdx.x, p = blockIdx.y, b = blockIdx.z;
    int c = threadIdx.x << 2;
    const float fw[4] = {1.f, 3.f, 3.f, 1.f};
    float4 acc = make_float4(0.f, 0.f, 0.f, 0.f);
#pragma unroll
    for (int eh = 0; eh < 4; eh++) {
        int pp = p + eh - 1;
        if ((unsigned)pp >= HOUT) continue;
        float4 row = make_float4(0.f, 0.f, 0.f, 0.f);
#pragma unroll
        for (int ew = 0; ew < 4; ew++) {
            int qq = q + ew - 1;
            if ((unsigned)qq >= WOUT) continue;
            float4 v = *(const float4*)&g_y[(((size_t)b * HOUT + pp) * WOUT + qq) * CH + c];
            row.x += v.x * fw[ew]; row.y += v.y * fw[ew];
            row.z += v.z * fw[ew]; row.w += v.w * fw[ew];
        }
        acc.x += row.x * fw[eh]; acc.y += row.y * fw[eh];
        acc.z += row.z * fw[eh]; acc.w += row.w * fw[eh];
    }
    const float inv16 = 0.0625f;  // outer([1,3,3,1]/8)^2 * gain4 => /16
    float4 dv = *(const float4*)&g_d1[b][c];
    float4 sn = *(const float4*)&sn1[c];
    float4 bb = *(const float4*)&bias1[c];
    float nz = noise1[((size_t)b * HOUT + p) * WOUT + q];
    float4 o;
    o.x = lrelu(acc.x * inv16 * dv.x + sn.x * nz + bb.x);
    o.y = lrelu(acc.y * inv16 * dv.y + sn.y * nz + bb.y);
    o.z = lrelu(acc.z * inv16 * dv.z + sn.z * nz + bb.z);
    o.w = lrelu(acc.w * inv16 * dv.w + sn.w * nz + bb.w);
    *(float4*)&g_x1[(((size_t)b * HOUT + p) * WOUT + q) * CH + c] = o;
}

// ---------------- 3x3 stride-1 SAME conv + demod + noise + bias + lrelu --------
__global__ __launch_bounds__(256) void k_conv2(const float* __restrict__ cw,
                                               const float* __restrict__ noise2,
                                               const float* __restrict__ sn2,
                                               const float* __restrict__ bias2,
                                               float* __restrict__ out) {
    __shared__ __align__(16) float sw_[9][16][64];
    __shared__ __align__(8) float sx[16][100];
    int tid = threadIdx.x;
    int coq = tid & 15, pxq = tid >> 4;
    int qu = pxq >> 2, qv = pxq & 3;
    int co0 = blockIdx.x * 64;
    int tp = blockIdx.y >> 3, tq = blockIdx.y & 7;
    int b = blockIdx.z;
    int p0 = tp * 8, q0 = tq * 8;
    const float wscale = 0.014731391274719742f;

    ull acc[2][2][2];
#pragma unroll
    for (int u = 0; u < 2; u++)
#pragma unroll
        for (int v = 0; v < 2; v++) { acc[u][v][0] = 0ull; acc[u][v][1] = 0ull; }

    for (int c0 = 0; c0 < CH; c0 += 16) {
        __syncthreads();
#pragma unroll
        for (int k = 0; k < 36; k++) {
            int idx = tid + k * 256;
            int co = idx & 63, ci = (idx >> 6) & 15, tap = idx >> 10;
            sw_[tap][ci][co] = cw[((size_t)tap * CH + c0 + ci) * CH + co0 + co] * wscale;
        }
        for (int idx = tid; idx < 100 * 16; idx += 256) {
            int ci = idx & 15, pos = idx >> 4;
            int r = pos / 10, cc = pos - r * 10;
            int gp = p0 - 1 + r, gq = q0 - 1 + cc;
            float v = 0.f;
            if ((unsigned)gp < HOUT && (unsigned)gq < WOUT)
                v = g_x1[(((size_t)b * HOUT + gp) * WOUT + gq) * CH + c0 + ci] * g_s2[b][c0 + ci];
            sx[ci][pos] = v;
        }
        __syncthreads();
#pragma unroll 2
        for (int ci = 0; ci < 16; ci++) {
            ull xp[4][4];
#pragma unroll
            for (int r = 0; r < 4; r++) {
                float2 t0 = *(const float2*)&sx[ci][(2 * qu + r) * 10 + 2 * qv];
                float2 t1 = *(const float2*)&sx[ci][(2 * qu + r) * 10 + 2 * qv + 2];
                xp[r][0] = pk(t0.x); xp[r][1] = pk(t0.y);
                xp[r][2] = pk(t1.x); xp[r][3] = pk(t1.y);
            }
#pragma unroll
            for (int dh = 0; dh < 3; dh++)
#pragma unroll
                for (int dw = 0; dw < 3; dw++) {
                    F4U wt;
                    wt.f = *(const float4*)&sw_[dh * 3 + dw][ci][coq << 2];
#pragma unroll
                    for (int u = 0; u < 2; u++)
#pragma unroll
                        for (int v = 0; v < 2; v++) {
                            ffma2(acc[u][v][0], xp[u + dh][v + dw], wt.u[0]);
                            ffma2(acc[u][v][1], xp[u + dh][v + dw], wt.u[1]);
                        }
                }
        }
    }
    int co = co0 + (coq << 2);
    F4U dv; dv.f = *(const float4*)&g_d2[b][co];
    F4U sn; sn.f = *(const float4*)&sn2[co];
    F4U bb; bb.f = *(const float4*)&bias2[co];
#pragma unroll
    for (int u = 0; u < 2; u++)
#pragma unroll
        for (int v = 0; v < 2; v++) {
            int p = p0 + 2 * qu + u, q = q0 + 2 * qv + v;
            float nz = noise2[((size_t)b * HOUT + p) * WOUT + q];
            F4U a;
            a.u[0] = acc[u][v][0];
            a.u[1] = acc[u][v][1];
            F4U o;
#pragma unroll
            for (int k = 0; k < 4; k++)
                o.s[k] = lrelu(a.s[k] * dv.s[k] + sn.s[k] * nz + bb.s[k]);
            *(float4*)&out[(((size_t)b * HOUT + p) * WOUT + q) * CH + co] = o.f;
        }
}

// ---------------- toRGB: 1x1 modconv (no demod) + bias + lrelu -----------------
__global__ void k_rgb(const float* __restrict__ x2, const float* __restrict__ wr,
                      const float* __restrict__ br, float* __restrict__ rgb) {
    int b = blockIdx.y, tid = threadIdx.x;
    __shared__ float wc[CH * 3];
    const float wscale = 0.044194173824159216f;  // 1/sqrt(512)
    for (int k = tid; k < CH * 3; k += 256) {
        int ci = k / 3;
        wc[k] = g_sr[b][ci] * wscale * wr[k];
    }
    __syncthreads();
    int warp = tid >> 5, lane = tid & 31;
    int pix = blockIdx.x * 8 + warp;
    const float* xp = x2 + ((size_t)b * HOUT * WOUT + pix) * CH;
    float a0 = 0.f, a1 = 0.f, a2 = 0.f;
    for (int ci = lane; ci < CH; ci += 32) {
        float v = xp[ci];
        a0 = fmaf(v, wc[ci * 3 + 0], a0);
        a1 = fmaf(v, wc[ci * 3 + 1], a1);
        a2 = fmaf(v, wc[ci * 3 + 2], a2);
    }
#pragma unroll
    for (int o = 16; o; o >>= 1) {
        a0 += __shfl_xor_sync(0xffffffffu, a0, o);
        a1 += __shfl_xor_sync(0xffffffffu, a1, o);
        a2 += __shfl_xor_sync(0xffffffffu, a2, o);
    }
    if (lane == 0) {
        size_t base = ((size_t)b * HOUT * WOUT + pix) * 3;
        rgb[base + 0] = lrelu(a0 + br[0]);
        rgb[base + 1] = lrelu(a1 + br[1]);
        rgb[base + 2] = lrelu(a2 + br[2]);
    }
}

// ---------------- launch --------------------------------------------------------
extern "C" void kernel_launch(void* const* d_in, const int* in_sizes, int n_in,
                              void* d_out, int out_size) {
    const float* x       = (const float*)d_in[0];
    const float* w       = (const float*)d_in[1];
    const float* noise1  = (const float*)d_in[2];
    const float* noise2  = (const float*)d_in[3];
    const float* fcl1_w  = (const float*)d_in[4];
    const float* fcl1_b  = (const float*)d_in[5];
    const float* conv1_w = (const float*)d_in[6];
    const float* sn1     = (const float*)d_in[7];
    const float* bias1   = (const float*)d_in[8];
    const float* fcl2_w  = (const float*)d_in[9];
    const float* fcl2_b  = (const float*)d_in[10];
    const float* conv2_w = (const float*)d_in[11];
    const float* sn2     = (const float*)d_in[12];
    const float* bias2   = (const float*)d_in[13];
    const float* fclr_w  = (const float*)d_in[14];
    const float* fclr_b  = (const float*)d_in[15];
    const float* convr_w = (const float*)d_in[16];
    const float* biasr   = (const float*)d_in[17];
    float* out = (float*)d_out;
    float* xpart = out;
    float* rgbpart = out + (size_t)BATCH * HOUT * WOUT * CH;

    k_styles<<<BATCH, 512>>>(w, fcl1_w, fcl1_b, 0);
    k_styles<<<BATCH, 512>>>(w, fcl2_w, fcl2_b, 1);
    k_styles<<<BATCH, 512>>>(w, fclr_w, fclr_b, 2);
    k_wsq<<<(CH * CH) / 256, 256>>>(conv1_w, conv2_w);
    k_demod<<<BATCH, 512>>>(0);
    k_demod<<<BATCH, 512>>>(1);
    k_convT<<<dim3(8, 64, BATCH), 256>>>(x, conv1_w);
    k_blur<<<dim3(WOUT, HOUT, BATCH), 128>>>(noise1, sn1, bias1);
    k_conv2<<<dim3(8, 64, BATCH), 256>>>(conv2_w, noise2, sn2, bias2, xpart);
    k_rgb<<<dim3(HOUT * WOUT / 8, BATCH), 256>>>(xpart, convr_w, biasr, rgbpart);
}

// round 4
// speedup vs baseline: 1.0008x; 1.0008x over previous
#include <cuda_runtime.h>
#include <cstdint>

#define BATCH 16
#define HIN 32
#define WIN 32
#define CH 512
#define HOUT 64
#define WOUT 64

typedef unsigned long long ull;

// ---------------- device scratch (allocation-free rule: static globals) ---------
__device__ float g_s1[BATCH][CH];
__device__ float g_s2[BATCH][CH];
__device__ float g_sr[BATCH][CH];
__device__ float g_d1[BATCH][CH];
__device__ float g_d2[BATCH][CH];
__device__ float g_wsq1[CH * CH];
__device__ float g_wsq2[CH * CH];
__device__ float g_y[(size_t)BATCH * HOUT * WOUT * CH];   // convT output, pre-blur
__device__ float g_x1[(size_t)BATCH * HOUT * WOUT * CH];  // style block 1 output

__device__ __forceinline__ float lrelu(float v) { return v > 0.f ? v : 0.2f * v; }

// pack a scalar into both halves of an f32x2 register pair
__device__ __forceinline__ ull pk(float x) {
    ull r;
    asm("mov.b64 %0, {%1, %1};" : "=l"(r) : "f"(x));
    return r;
}
// packed fp32 FMA (FFMA2) — 2 MACs/lane/instr, PTX-only on sm_103a
__device__ __forceinline__ void ffma2(ull& d, ull a, ull b) {
    asm("fma.rn.f32x2 %0, %1, %2, %0;" : "+l"(d) : "l"(a), "l"(b));
}

union F4U {
    float4 f;
    ull u[2];
    float s[4];
};

// ---------------- styles: s = w @ (fw/sqrt(512)) + fb --------------------------
__global__ void k_styles(const float* __restrict__ w, const float* __restrict__ fw,
                         const float* __restrict__ fb, int which) {
    int b = blockIdx.x, co = threadIdx.x;
    __shared__ float sw_[CH];
    sw_[co] = w[b * CH + co];
    __syncthreads();
    float acc = 0.f;
#pragma unroll 4
    for (int ci = 0; ci < CH; ci++) acc = fmaf(sw_[ci], fw[ci * CH + co], acc);
    float v = acc * 0.044194173824159216f + fb[co];  // 1/sqrt(512)
    if (which == 0) g_s1[b][co] = v;
    else if (which == 1) g_s2[b][co] = v;
    else g_sr[b][co] = v;
}

// ---------------- per-(ci,co) squared-weight sums for demod --------------------
__global__ void k_wsq(const float* __restrict__ w1, const float* __restrict__ w2) {
    int idx = blockIdx.x * 256 + threadIdx.x;  // < CH*CH
    const float ws2 = 1.0f / 4608.0f;          // wscale^2 = 1/(9*512)
    float a1 = 0.f, a2 = 0.f;
#pragma unroll
    for (int t = 0; t < 9; t++) {
        float v1 = w1[(size_t)t * CH * CH + idx];
        a1 = fmaf(v1, v1, a1);
        float v2 = w2[(size_t)t * CH * CH + idx];
        a2 = fmaf(v2, v2, a2);
    }
    g_wsq1[idx] = a1 * ws2;
    g_wsq2[idx] = a2 * ws2;
}

// ---------------- demod: d[b,co] = rsqrt(sum_ci s^2 * wsq + 1e-8) --------------
__global__ void k_demod(int which) {
    int b = blockIdx.x, co = threadIdx.x;
    __shared__ float ss[CH];
    float s = which ? g_s2[b][co] : g_s1[b][co];
    ss[co] = s * s;
    __syncthreads();
    const float* wsq = which ? g_wsq2 : g_wsq1;
    float acc = 0.f;
#pragma unroll 4
    for (int ci = 0; ci < CH; ci++) acc = fmaf(ss[ci], wsq[ci * CH + co], acc);
    float d = rsqrtf(acc + 1e-8f);
    if (which) g_d2[b][co] = d;
    else g_d1[b][co] = d;
}

// ---------------- conv_transpose 3x3 stride 2 (parity-decomposed) --------------
// y[p,q,co] = sum over dilated-input taps; p even: dh in {0,2}; p odd: dh=1.
// Per 2x2 output quad at (2i,2j): needs input (i-1..i, j-1..j).
__global__ __launch_bounds__(256) void k_convT(const float* __restrict__ x,
                                               const float* __restrict__ cw) {
    __shared__ __align__(16) float sw_[9][16][64];
    __shared__ float sx[16][25];
    int tid = threadIdx.x;
    int coq = tid & 15, pxq = tid >> 4;
    int qu = pxq >> 2, qv = pxq & 3;
    int co0 = blockIdx.x * 64;
    int tp = blockIdx.y >> 3, tq = blockIdx.y & 7;
    int b = blockIdx.z;
    int p0 = tp * 8, q0 = tq * 8;
    int i0 = (p0 >> 1) - 1, j0 = (q0 >> 1) - 1;
    const float wscale = 0.014731391274719742f;  // 1/sqrt(9*512)

    ull acc[4][2];
#pragma unroll
    for (int i = 0; i < 4; i++) { acc[i][0] = 0ull; acc[i][1] = 0ull; }

    for (int c0 = 0; c0 < CH; c0 += 16) {
        __syncthreads();
#pragma unroll
        for (int k = 0; k < 36; k++) {  // 9*16*64 = 36*256
            int idx = tid + k * 256;
            int co = idx & 63, ci = (idx >> 6) & 15, tap = idx >> 10;
            sw_[tap][ci][co] = cw[((size_t)tap * CH + c0 + ci) * CH + co0 + co] * wscale;
        }
        for (int idx = tid; idx < 25 * 16; idx += 256) {
            int ci = idx & 15, pos = idx >> 4;
            int r = pos / 5, cc = pos - r * 5;
            int gi = i0 + r, gj = j0 + cc;
            float v = 0.f;
            if ((unsigned)gi < HIN && (unsigned)gj < WIN)
                v = x[(((size_t)b * HIN + gi) * WIN + gj) * CH + c0 + ci] * g_s1[b][c0 + ci];
            sx[ci][pos] = v;
        }
        __syncthreads();
#pragma unroll 4
        for (int ci = 0; ci < 16; ci++) {
            float x00 = sx[ci][qu * 5 + qv],       x01 = sx[ci][qu * 5 + qv + 1];
            float x10 = sx[ci][(qu + 1) * 5 + qv], x11 = sx[ci][(qu + 1) * 5 + qv + 1];
            ull X00 = pk(x00), X01 = pk(x01), X10 = pk(x10), X11 = pk(x11);
            F4U wt[9];
#pragma unroll
            for (int t = 0; t < 9; t++) wt[t].f = *(const float4*)&sw_[t][ci][coq << 2];
            // ee (p even, q even): taps (0,0),(0,2),(2,0),(2,2)
            ffma2(acc[0][0], X00, wt[0].u[0]); ffma2(acc[0][1], X00, wt[0].u[1]);
            ffma2(acc[0][0], X01, wt[2].u[0]); ffma2(acc[0][1], X01, wt[2].u[1]);
            ffma2(acc[0][0], X10, wt[6].u[0]); ffma2(acc[0][1], X10, wt[6].u[1]);
            ffma2(acc[0][0], X11, wt[8].u[0]); ffma2(acc[0][1], X11, wt[8].u[1]);
            // eo: taps (0,1),(2,1)
            ffma2(acc[1][0], X01, wt[1].u[0]); ffma2(acc[1][1], X01, wt[1].u[1]);
            ffma2(acc[1][0], X11, wt[7].u[0]); ffma2(acc[1][1], X11, wt[7].u[1]);
            // oe: taps (1,0),(1,2)
            ffma2(acc[2][0], X10, wt[3].u[0]); ffma2(acc[2][1], X10, wt[3].u[1]);
            ffma2(acc[2][0], X11, wt[5].u[0]); ffma2(acc[2][1], X11, wt[5].u[1]);
            // oo: tap (1,1)
            ffma2(acc[3][0], X11, wt[4].u[0]); ffma2(acc[3][1], X11, wt[4].u[1]);
        }
    }
#pragma unroll
    for (int u = 0; u < 2; u++)
#pragma unroll
        for (int v = 0; v < 2; v++) {
            F4U o;
            o.u[0] = acc[u * 2 + v][0];
            o.u[1] = acc[u * 2 + v][1];
            int p = p0 + 2 * qu + u, q = q0 + 2 * qv + v;
            *(float4*)&g_y[(((size_t)b * HOUT + p) * WOUT + q) * CH + co0 + (coq << 2)] = o.f;
        }
}

// ---------------- blur (4x4 FIR, pad lo=1 hi=2) + demod + noise + bias + lrelu --
__global__ void k_blur(const float* __restrict__ noise1, const float* __restrict__ sn1,
                       const float* __restrict__ bias1) {
    int q = blockIdx.x, p = blockIdx.y, b = blockIdx.z;
    int c = threadIdx.x << 2;
    const float fw[4] = {1.f, 3.f, 3.f, 1.f};
    float4 acc = make_float4(0.f, 0.f, 0.f, 0.f);
#pragma unroll
    for (int eh = 0; eh < 4; eh++) {
        int pp = p + eh - 1;
        if ((unsigned)pp >= HOUT) continue;
        float4 row = make_float4(0.f, 0.f, 0.f, 0.f);
#pragma unroll
        for (int ew = 0; ew < 4; ew++) {
            int qq = q + ew - 1;
            if ((unsigned)qq >= WOUT) continue;
            float4 v = *(const float4*)&g_y[(((size_t)b * HOUT + pp) * WOUT + qq) * CH + c];
            row.x += v.x * fw[ew]; row.y += v.y * fw[ew];
            row.z += v.z * fw[ew]; row.w += v.w * fw[ew];
        }
        acc.x += row.x * fw[eh]; acc.y += row.y * fw[eh];
        acc.z += row.z * fw[eh]; acc.w += row.w * fw[eh];
    }
    const float inv16 = 0.0625f;  // outer([1,3,3,1]/8)^2 * gain4 => /16
    float4 dv = *(const float4*)&g_d1[b][c];
    float4 sn = *(const float4*)&sn1[c];
    float4 bb = *(const float4*)&bias1[c];
    float nz = noise1[((size_t)b * HOUT + p) * WOUT + q];
    float4 o;
    o.x = lrelu(acc.x * inv16 * dv.x + sn.x * nz + bb.x);
    o.y = lrelu(acc.y * inv16 * dv.y + sn.y * nz + bb.y);
    o.z = lrelu(acc.z * inv16 * dv.z + sn.z * nz + bb.z);
    o.w = lrelu(acc.w * inv16 * dv.w + sn.w * nz + bb.w);
    *(float4*)&g_x1[(((size_t)b * HOUT + p) * WOUT + q) * CH + c] = o;
}

// ---------------- 3x3 stride-1 SAME conv + demod + noise + bias + lrelu --------
__global__ __launch_bounds__(256) void k_conv2(const float* __restrict__ cw,
                                               const float* __restrict__ noise2,
                                               const float* __restrict__ sn2,
                                               const float* __restrict__ bias2,
                                               float* __restrict__ out) {
    __shared__ __align__(16) float sw_[9][16][64];
    __shared__ __align__(8) float sx[16][100];
    int tid = threadIdx.x;
    int coq = tid & 15, pxq = tid >> 4;
    int qu = pxq >> 2, qv = pxq & 3;
    int co0 = blockIdx.x * 64;
    int tp = blockIdx.y >> 3, tq = blockIdx.y & 7;
    int b = blockIdx.z;
    int p0 = tp * 8, q0 = tq * 8;
    const float wscale = 0.014731391274719742f;

    ull acc[2][2][2];
#pragma unroll
    for (int u = 0; u < 2; u++)
#pragma unroll
        for (int v = 0; v < 2; v++) { acc[u][v][0] = 0ull; acc[u][v][1] = 0ull; }

    for (int c0 = 0; c0 < CH; c0 += 16) {
        __syncthreads();
#pragma unroll
        for (int k = 0; k < 36; k++) {
            int idx = tid + k * 256;
            int co = idx & 63, ci = (idx >> 6) & 15, tap = idx >> 10;
            sw_[tap][ci][co] = cw[((size_t)tap * CH + c0 + ci) * CH + co0 + co] * wscale;
        }
        for (int idx = tid; idx < 100 * 16; idx += 256) {
            int ci = idx & 15, pos = idx >> 4;
            int r = pos / 10, cc = pos - r * 10;
            int gp = p0 - 1 + r, gq = q0 - 1 + cc;
            float v = 0.f;
            if ((unsigned)gp < HOUT && (unsigned)gq < WOUT)
                v = g_x1[(((size_t)b * HOUT + gp) * WOUT + gq) * CH + c0 + ci] * g_s2[b][c0 + ci];
            sx[ci][pos] = v;
        }
        __syncthreads();
#pragma unroll 2
        for (int ci = 0; ci < 16; ci++) {
            ull xp[4][4];
#pragma unroll
            for (int r = 0; r < 4; r++) {
                float2 t0 = *(const float2*)&sx[ci][(2 * qu + r) * 10 + 2 * qv];
                float2 t1 = *(const float2*)&sx[ci][(2 * qu + r) * 10 + 2 * qv + 2];
                xp[r][0] = pk(t0.x); xp[r][1] = pk(t0.y);
                xp[r][2] = pk(t1.x); xp[r][3] = pk(t1.y);
            }
#pragma unroll
            for (int dh = 0; dh < 3; dh++)
#pragma unroll
                for (int dw = 0; dw < 3; dw++) {
                    F4U wt;
                    wt.f = *(const float4*)&sw_[dh * 3 + dw][ci][coq << 2];
#pragma unroll
                    for (int u = 0; u < 2; u++)
#pragma unroll
                        for (int v = 0; v < 2; v++) {
                            ffma2(acc[u][v][0], xp[u + dh][v + dw], wt.u[0]);
                            ffma2(acc[u][v][1], xp[u + dh][v + dw], wt.u[1]);
                        }
                }
        }
    }
    int co = co0 + (coq << 2);
    F4U dv; dv.f = *(const float4*)&g_d2[b][co];
    F4U sn; sn.f = *(const float4*)&sn2[co];
    F4U bb; bb.f = *(const float4*)&bias2[co];
#pragma unroll
    for (int u = 0; u < 2; u++)
#pragma unroll
        for (int v = 0; v < 2; v++) {
            int p = p0 + 2 * qu + u, q = q0 + 2 * qv + v;
            float nz = noise2[((size_t)b * HOUT + p) * WOUT + q];
            F4U a;
            a.u[0] = acc[u][v][0];
            a.u[1] = acc[u][v][1];
            F4U o;
#pragma unroll
            for (int k = 0; k < 4; k++)
                o.s[k] = lrelu(a.s[k] * dv.s[k] + sn.s[k] * nz + bb.s[k]);
            *(float4*)&out[(((size_t)b * HOUT + p) * WOUT + q) * CH + co] = o.f;
        }
}

// ---------------- toRGB: 1x1 modconv (no demod) + bias + lrelu -----------------
__global__ void k_rgb(const float* __restrict__ x2, const float* __restrict__ wr,
                      const float* __restrict__ br, float* __restrict__ rgb) {
    int b = blockIdx.y, tid = threadIdx.x;
    __shared__ float wc[CH * 3];
    const float wscale = 0.044194173824159216f;  // 1/sqrt(512)
    for (int k = tid; k < CH * 3; k += 256) {
        int ci = k / 3;
        wc[k] = g_sr[b][ci] * wscale * wr[k];
    }
    __syncthreads();
    int warp = tid >> 5, lane = tid & 31;
    int pix = blockIdx.x * 8 + warp;
    const float* xp = x2 + ((size_t)b * HOUT * WOUT + pix) * CH;
    float a0 = 0.f, a1 = 0.f, a2 = 0.f;
    for (int ci = lane; ci < CH; ci += 32) {
        float v = xp[ci];
        a0 = fmaf(v, wc[ci * 3 + 0], a0);
        a1 = fmaf(v, wc[ci * 3 + 1], a1);
        a2 = fmaf(v, wc[ci * 3 + 2], a2);
    }
#pragma unroll
    for (int o = 16; o; o >>= 1) {
        a0 += __shfl_xor_sync(0xffffffffu, a0, o);
        a1 += __shfl_xor_sync(0xffffffffu, a1, o);
        a2 += __shfl_xor_sync(0xffffffffu, a2, o);
    }
    if (lane == 0) {
        size_t base = ((size_t)b * HOUT * WOUT + pix) * 3;
        rgb[base + 0] = lrelu(a0 + br[0]);
        rgb[base + 1] = lrelu(a1 + br[1]);
        rgb[base + 2] = lrelu(a2 + br[2]);
    }
}

// ---------------- launch --------------------------------------------------------
extern "C" void kernel_launch(void* const* d_in, const int* in_sizes, int n_in,
                              void* d_out, int out_size) {
    const float* x       = (const float*)d_in[0];
    const float* w       = (const float*)d_in[1];
    const float* noise1  = (const float*)d_in[2];
    const float* noise2  = (const float*)d_in[3];
    const float* fcl1_w  = (const float*)d_in[4];
    const float* fcl1_b  = (const float*)d_in[5];
    const float* conv1_w = (const float*)d_in[6];
    const float* sn1     = (const float*)d_in[7];
    const float* bias1   = (const float*)d_in[8];
    const float* fcl2_w  = (const float*)d_in[9];
    const float* fcl2_b  = (const float*)d_in[10];
    const float* conv2_w = (const float*)d_in[11];
    const float* sn2     = (const float*)d_in[12];
    const float* bias2   = (const float*)d_in[13];
    const float* fclr_w  = (const float*)d_in[14];
    const float* fclr_b  = (const float*)d_in[15];
    const float* convr_w = (const float*)d_in[16];
    const float* biasr   = (const float*)d_in[17];
    float* out = (float*)d_out;
    float* xpart = out;
    float* rgbpart = out + (size_t)BATCH * HOUT * WOUT * CH;

    k_styles<<<BATCH, 512>>>(w, fcl1_w, fcl1_b, 0);
    k_styles<<<BATCH, 512>>>(w, fcl2_w, fcl2_b, 1);
    k_styles<<<BATCH, 512>>>(w, fclr_w, fclr_b, 2);
    k_wsq<<<(CH * CH) / 256, 256>>>(conv1_w, conv2_w);
    k_demod<<<BATCH, 512>>>(0);
    k_demod<<<BATCH, 512>>>(1);
    k_convT<<<dim3(8, 64, BATCH), 256>>>(x, conv1_w);
    k_blur<<<dim3(WOUT, HOUT, BATCH), 128>>>(noise1, sn1, bias1);
    k_conv2<<<dim3(8, 64, BATCH), 256>>>(conv2_w, noise2, sn2, bias2, xpart);
    k_rgb<<<dim3(HOUT * WOUT / 8, BATCH), 256>>>(xpart, convr_w, biasr, rgbpart);
}

// round 7
// speedup vs baseline: 1.2781x; 1.2770x over previous
#include <cuda_runtime.h>
#include <cstdint>

#define BATCH 16
#define HIN 32
#define WIN 32
#define CH 512
#define HOUT 64
#define WOUT 64

__device__ float g_s1[BATCH][CH];
__device__ float g_s2[BATCH][CH];
__device__ float g_sr[BATCH][CH];
__device__ float g_d1[BATCH][CH];
__device__ float g_d2[BATCH][CH];
__device__ float g_wsq1[CH * CH];
__device__ float g_wsq2[CH * CH];
__device__ float g_y[(size_t)BATCH * HOUT * WOUT * CH];
__device__ float g_x1[(size_t)BATCH * HOUT * WOUT * CH];

__device__ __forceinline__ float lrelu(float v) { return v > 0.f ? v : 0.2f * v; }

__device__ __forceinline__ uint32_t smem_u32(const void* p) {
    uint32_t a;
    asm("{ .reg .u64 t; cvta.to.shared.u64 t, %1; cvt.u32.u64 %0, t; }" : "=r"(a) : "l"(p));
    return a;
}
__device__ __forceinline__ uint32_t tf32u(float x) {
    uint32_t r;
    asm("cvt.rna.tf32.f32 %0, %1;" : "=r"(r) : "f"(x));
    return r;
}
// m16n8k8 tf32 MMA, D += A*B (fp32 accum)
__device__ __forceinline__ void mma8(float* d, const uint32_t* a, uint32_t b0, uint32_t b1) {
    asm volatile(
        "mma.sync.aligned.m16n8k8.row.col.f32.tf32.tf32.f32 "
        "{%0,%1,%2,%3},{%4,%5,%6,%7},{%8,%9},{%0,%1,%2,%3};"
        : "+f"(d[0]), "+f"(d[1]), "+f"(d[2]), "+f"(d[3])
        : "r"(a[0]), "r"(a[1]), "r"(a[2]), "r"(a[3]), "r"(b0), "r"(b1));
}
__device__ __forceinline__ void cpa(uint32_t dst, const float* src, uint32_t sz) {
    asm volatile("cp.async.cg.shared.global [%0], [%1], 16, %2;"
                 :: "r"(dst), "l"(src), "r"(sz) : "memory");
}
#define CP_COMMIT() asm volatile("cp.async.commit_group;" ::: "memory")
template <int N>
__device__ __forceinline__ void cp_wait() {
    asm volatile("cp.async.wait_group %0;" :: "n"(N) : "memory");
}

// ---------------- fused styles (3 FC layers), grid (BATCH, 3) -------------------
__global__ void k_styles(const float* __restrict__ w,
                         const float* __restrict__ f1w, const float* __restrict__ f1b,
                         const float* __restrict__ f2w, const float* __restrict__ f2b,
                         const float* __restrict__ frw, const float* __restrict__ frb) {
    int b = blockIdx.x, which = blockIdx.y, co = threadIdx.x;
    const float* fw = which == 0 ? f1w : (which == 1 ? f2w : frw);
    const float* fb = which == 0 ? f1b : (which == 1 ? f2b : frb);
    __shared__ float sw_[CH];
    sw_[co] = w[b * CH + co];
    __syncthreads();
    float acc = 0.f;
#pragma unroll 4
    for (int ci = 0; ci < CH; ci++) acc = fmaf(sw_[ci], fw[ci * CH + co], acc);
    float v = acc * 0.044194173824159216f + fb[co];
    if (which == 0) g_s1[b][co] = v;
    else if (which == 1) g_s2[b][co] = v;
    else g_sr[b][co] = v;
}

__global__ void k_wsq(const float* __restrict__ w1, const float* __restrict__ w2) {
    int idx = blockIdx.x * 256 + threadIdx.x;
    const float ws2 = 1.0f / 4608.0f;
    float a1 = 0.f, a2 = 0.f;
#pragma unroll
    for (int t = 0; t < 9; t++) {
        float v1 = w1[(size_t)t * CH * CH + idx];
        a1 = fmaf(v1, v1, a1);
        float v2 = w2[(size_t)t * CH * CH + idx];
        a2 = fmaf(v2, v2, a2);
    }
    g_wsq1[idx] = a1 * ws2;
    g_wsq2[idx] = a2 * ws2;
}

// grid (BATCH, 2)
__global__ void k_demod() {
    int b = blockIdx.x, which = blockIdx.y, co = threadIdx.x;
    __shared__ float ss[CH];
    float s = which ? g_s2[b][co] : g_s1[b][co];
    ss[co] = s * s;
    __syncthreads();
    const float* wsq = which ? g_wsq2 : g_wsq1;
    float acc = 0.f;
#pragma unroll 4
    for (int ci = 0; ci < CH; ci++) acc = fmaf(ss[ci], wsq[ci * CH + co], acc);
    float d = rsqrtf(acc + 1e-8f);
    if (which) g_d2[b][co] = d;
    else g_d1[b][co] = d;
}

struct Taps { int n; int t[9]; int di[9]; int dj[9]; };

// Tiled implicit-GEMM conv via mma.sync tf32 (3-term fp32 split).
// MODE 0: convT parity class -> g_y raw at (2i+uo, 2j+vo). MODE 1: conv2 + epilogue -> outp.
// CTA: M=128 pixels (8 rows x 16 cols) x N=128 couts. 8 warps: 4 along M x 2 along N.
#define ASTR 36
#define BSTR 136
#define ASZ (128 * ASTR)
#define BSZ (32 * BSTR)

template <int MODE>
__global__ __launch_bounds__(256) void k_gemm(
    const float* __restrict__ xin, const float* __restrict__ cw, Taps taps,
    int uo, int vo, const float* __restrict__ noise, const float* __restrict__ snp,
    const float* __restrict__ biasp, float* __restrict__ outp) {
    constexpr int HI = MODE ? HOUT : HIN;
    constexpr int WI = MODE ? WOUT : WIN;
    extern __shared__ float sm[];
    __shared__ float s_mul[CH];
    __shared__ float s_dv[128], s_sn[128], s_bb[128];

    const int tid = threadIdx.x, lane = tid & 31, wid = tid >> 5;
    const int wm = wid & 3, wn = wid >> 2;
    const int b = blockIdx.z, co0 = blockIdx.x * 128;
    int pb, qb;
    if (MODE) { pb = (blockIdx.y >> 2) * 8; qb = (blockIdx.y & 3) * 16; }
    else      { pb = (blockIdx.y >> 1) * 8; qb = (blockIdx.y & 1) * 16; }

    const float* src = MODE ? &g_x1[0] : xin;
    const float* sty = MODE ? g_s2[b] : g_s1[b];
    const float wscale = 0.014731391274719742f;  // 1/sqrt(9*512)
    for (int i = tid; i < CH; i += 256) s_mul[i] = sty[i] * wscale;
    if (MODE && tid < 128) {
        s_dv[tid] = g_d2[b][co0 + tid];
        s_sn[tid] = snp[co0 + tid];
        s_bb[tid] = biasp[co0 + tid];
    }
    __syncthreads();

    float* Ab0 = sm;
    float* Ab1 = sm + ASZ;
    float* Bb0 = sm + 2 * ASZ;
    float* Bb1 = sm + 2 * ASZ + BSZ;
    const uint32_t Aadr[2] = {smem_u32(Ab0), smem_u32(Ab1)};
    const uint32_t Badr[2] = {smem_u32(Bb0), smem_u32(Bb1)};
    const float* Abuf[2] = {Ab0, Ab1};
    const float* Bbuf[2] = {Bb0, Bb1};

    // per-thread staging coords
    const int apx = tid >> 1, ah16 = (tid & 1) * 16;  // A: pixel, 16-float half
    const int apr = apx >> 4, apc = apx & 15;
    const int bk = tid >> 3, bseg = (tid & 7) * 16;   // B: k-row, 16-float seg

    float acc[2][8][4];
#pragma unroll
    for (int i = 0; i < 2; i++)
#pragma unroll
        for (int j = 0; j < 8; j++)
#pragma unroll
            for (int k = 0; k < 4; k++) acc[i][j][k] = 0.f;

    const int nkb = taps.n * 16;

#define STAGE(BUF, TP, CI0)                                                          \
    do {                                                                             \
        int di_ = taps.di[TP], dj_ = taps.dj[TP], t_ = taps.t[TP];                   \
        int gp_ = pb + apr + di_, gq_ = qb + apc + dj_;                              \
        bool ok_ = (unsigned)gp_ < (unsigned)HI && (unsigned)gq_ < (unsigned)WI;     \
        const float* s_ = ok_ ?                                                      \
            &src[(((size_t)b * HI + gp_) * WI + gq_) * CH + (CI0) + ah16] : src;     \
        uint32_t d_ = Aadr[BUF] + (uint32_t)(apx * ASTR + ah16) * 4;                 \
        uint32_t sz_ = ok_ ? 16u : 0u;                                               \
        cpa(d_, s_, sz_); cpa(d_ + 16, s_ + 4, sz_);                                 \
        cpa(d_ + 32, s_ + 8, sz_); cpa(d_ + 48, s_ + 12, sz_);                       \
        const float* sb_ = &cw[(size_t)t_ * CH * CH + (size_t)((CI0) + bk) * CH +    \
                               co0 + bseg];                                          \
        uint32_t db_ = Badr[BUF] + (uint32_t)(bk * BSTR + bseg) * 4;                 \
        cpa(db_, sb_, 16); cpa(db_ + 16, sb_ + 4, 16);                               \
        cpa(db_ + 32, sb_ + 8, 16); cpa(db_ + 48, sb_ + 12, 16);                     \
    } while (0)

    STAGE(0, 0, 0);
    CP_COMMIT();

    for (int kb = 0; kb < nkb; kb++) {
        const int buf = kb & 1;
        if (kb + 1 < nkb) {
            int tp = (kb + 1) >> 4, ci0n = ((kb + 1) & 15) << 5;
            STAGE(buf ^ 1, tp, ci0n);
            CP_COMMIT();
            cp_wait<1>();
        } else {
            cp_wait<0>();
        }
        __syncthreads();
        const int ci0 = (kb & 15) << 5;
        const float* Ab = Abuf[buf];
        const float* Bb = Bbuf[buf];
#pragma unroll
        for (int kc = 0; kc < 4; kc++) {
            uint32_t ahf[2][4], alf[2][4];
#pragma unroll
            for (int mt = 0; mt < 2; mt++)
#pragma unroll
                for (int v = 0; v < 4; v++) {
                    int row = wm * 32 + mt * 16 + (lane >> 2) + ((v & 1) << 3);
                    int kk = kc * 8 + (lane & 3) + ((v >> 1) << 2);
                    float a = Ab[row * ASTR + kk] * s_mul[ci0 + kk];
                    uint32_t h = tf32u(a);
                    ahf[mt][v] = h;
                    alf[mt][v] = tf32u(a - __uint_as_float(h));
                }
#pragma unroll
            for (int nt = 0; nt < 8; nt++) {
                int n = wn * 64 + nt * 8 + (lane >> 2);
                int kk = kc * 8 + (lane & 3);
                float b0 = Bb[kk * BSTR + n];
                float b1 = Bb[(kk + 4) * BSTR + n];
                uint32_t bh0 = tf32u(b0), bh1 = tf32u(b1);
                uint32_t bl0 = tf32u(b0 - __uint_as_float(bh0));
                uint32_t bl1 = tf32u(b1 - __uint_as_float(bh1));
#pragma unroll
                for (int mt = 0; mt < 2; mt++) {
                    mma8(acc[mt][nt], ahf[mt], bh0, bh1);
                    mma8(acc[mt][nt], ahf[mt], bl0, bl1);
                    mma8(acc[mt][nt], alf[mt], bh0, bh1);
                }
            }
        }
        __syncthreads();
    }
#undef STAGE

    // epilogue: D frag c0,c1 at (row=lane>>2, col=2*(lane&3)); c2,c3 at row+8
    const int r0 = wm * 32 + (lane >> 2);
    const int cb = wn * 64 + (lane & 3) * 2;
#pragma unroll
    for (int mt = 0; mt < 2; mt++)
#pragma unroll
        for (int half = 0; half < 2; half++) {
            int m = r0 + mt * 16 + half * 8;
            int pr = m >> 4, pc = m & 15;
            int p, q;
            if (MODE) { p = pb + pr; q = qb + pc; }
            else      { p = 2 * (pb + pr) + uo; q = 2 * (qb + pc) + vo; }
            size_t base = (((size_t)b * HOUT + p) * WOUT + q) * CH + co0;
            float nz = MODE ? noise[((size_t)b * HOUT + p) * WOUT + q] : 0.f;
#pragma unroll
            for (int nt = 0; nt < 8; nt++) {
                int col = cb + nt * 8;
                float v0 = acc[mt][nt][half * 2 + 0];
                float v1 = acc[mt][nt][half * 2 + 1];
                float2 o;
                if (MODE) {
                    o.x = lrelu(v0 * s_dv[col] + s_sn[col] * nz + s_bb[col]);
                    o.y = lrelu(v1 * s_dv[col + 1] + s_sn[col + 1] * nz + s_bb[col + 1]);
                    *(float2*)&outp[base + col] = o;
                } else {
                    o.x = v0; o.y = v1;
                    *(float2*)&g_y[base + col] = o;
                }
            }
        }
}

__global__ void k_blur(const float* __restrict__ noise1, const float* __restrict__ sn1,
                       const float* __restrict__ bias1) {
    int q = blockIdx.x, p = blockIdx.y, b = blockIdx.z;
    int c = threadIdx.x << 2;
    const float fw[4] = {1.f, 3.f, 3.f, 1.f};
    float4 acc = make_float4(0.f, 0.f, 0.f, 0.f);
#pragma unroll
    for (int eh = 0; eh < 4; eh++) {
        int pp = p + eh - 1;
        if ((unsigned)pp >= HOUT) continue;
        float4 row = make_float4(0.f, 0.f, 0.f, 0.f);
#pragma unroll
        for (int ew = 0; ew < 4; ew++) {
            int qq = q + ew - 1;
            if ((unsigned)qq >= WOUT) continue;
            float4 v = *(const float4*)&g_y[(((size_t)b * HOUT + pp) * WOUT + qq) * CH + c];
            row.x += v.x * fw[ew]; row.y += v.y * fw[ew];
            row.z += v.z * fw[ew]; row.w += v.w * fw[ew];
        }
        acc.x += row.x * fw[eh]; acc.y += row.y * fw[eh];
        acc.z += row.z * fw[eh]; acc.w += row.w * fw[eh];
    }
    const float inv16 = 0.0625f;
    float4 dv = *(const float4*)&g_d1[b][c];
    float4 sn = *(const float4*)&sn1[c];
    float4 bb = *(const float4*)&bias1[c];
    float nz = noise1[((size_t)b * HOUT + p) * WOUT + q];
    float4 o;
    o.x = lrelu(acc.x * inv16 * dv.x + sn.x * nz + bb.x);
    o.y = lrelu(acc.y * inv16 * dv.y + sn.y * nz + bb.y);
    o.z = lrelu(acc.z * inv16 * dv.z + sn.z * nz + bb.z);
    o.w = lrelu(acc.w * inv16 * dv.w + sn.w * nz + bb.w);
    *(float4*)&g_x1[(((size_t)b * HOUT + p) * WOUT + q) * CH + c] = o;
}

__global__ void k_rgb(const float* __restrict__ x2, const float* __restrict__ wr,
                      const float* __restrict__ br, float* __restrict__ rgb) {
    int b = blockIdx.y, tid = threadIdx.x;
    __shared__ float wc[CH * 3];
    const float wscale = 0.044194173824159216f;
    for (int k = tid; k < CH * 3; k += 256) {
        int ci = k / 3;
        wc[k] = g_sr[b][ci] * wscale * wr[k];
    }
    __syncthreads();
    int warp = tid >> 5, lane = tid & 31;
    int pix = blockIdx.x * 8 + warp;
    const float* xp = x2 + ((size_t)b * HOUT * WOUT + pix) * CH;
    float a0 = 0.f, a1 = 0.f, a2 = 0.f;
    for (int ci = lane; ci < CH; ci += 32) {
        float v = xp[ci];
        a0 = fmaf(v, wc[ci * 3 + 0], a0);
        a1 = fmaf(v, wc[ci * 3 + 1], a1);
        a2 = fmaf(v, wc[ci * 3 + 2], a2);
    }
#pragma unroll
    for (int o = 16; o; o >>= 1) {
        a0 += __shfl_xor_sync(0xffffffffu, a0, o);
        a1 += __shfl_xor_sync(0xffffffffu, a1, o);
        a2 += __shfl_xor_sync(0xffffffffu, a2, o);
    }
    if (lane == 0) {
        size_t base = ((size_t)b * HOUT * WOUT + pix) * 3;
        rgb[base + 0] = lrelu(a0 + br[0]);
        rgb[base + 1] = lrelu(a1 + br[1]);
        rgb[base + 2] = lrelu(a2 + br[2]);
    }
}

extern "C" void kernel_launch(void* const* d_in, const int* in_sizes, int n_in,
                              void* d_out, int out_size) {
    const float* x       = (const float*)d_in[0];
    const float* w       = (const float*)d_in[1];
    const float* noise1  = (const float*)d_in[2];
    const float* noise2  = (const float*)d_in[3];
    const float* fcl1_w  = (const float*)d_in[4];
    const float* fcl1_b  = (const float*)d_in[5];
    const float* conv1_w = (const float*)d_in[6];
    const float* sn1     = (const float*)d_in[7];
    const float* bias1   = (const float*)d_in[8];
    const float* fcl2_w  = (const float*)d_in[9];
    const float* fcl2_b  = (const float*)d_in[10];
    const float* conv2_w = (const float*)d_in[11];
    const float* sn2     = (const float*)d_in[12];
    const float* bias2   = (const float*)d_in[13];
    const float* fclr_w  = (const float*)d_in[14];
    const float* fclr_b  = (const float*)d_in[15];
    const float* convr_w = (const float*)d_in[16];
    const float* biasr   = (const float*)d_in[17];
    float* out = (float*)d_out;
    float* xpart = out;
    float* rgbpart = out + (size_t)BATCH * HOUT * WOUT * CH;

    const int SMEM = (2 * ASZ + 2 * BSZ) * 4;  // 71680 B
    cudaFuncSetAttribute(k_gemm<0>, cudaFuncAttributeMaxDynamicSharedMemorySize, SMEM);
    cudaFuncSetAttribute(k_gemm<1>, cudaFuncAttributeMaxDynamicSharedMemorySize, SMEM);

    k_styles<<<dim3(BATCH, 3), 512>>>(w, fcl1_w, fcl1_b, fcl2_w, fcl2_b, fclr_w, fclr_b);
    k_wsq<<<(CH * CH) / 256, 256>>>(conv1_w, conv2_w);
    k_demod<<<dim3(BATCH, 2), 512>>>();

    // convT parity classes (validated in R2): y[2i+u,2j+v] = sum_t w[t]*x[i+di, j+dj]
    Taps tee; tee.n = 4;
    tee.t[0] = 0; tee.di[0] = -1; tee.dj[0] = -1;
    tee.t[1] = 2; tee.di[1] = -1; tee.dj[1] = 0;
    tee.t[2] = 6; tee.di[2] = 0;  tee.dj[2] = -1;
    tee.t[3] = 8; tee.di[3] = 0;  tee.dj[3] = 0;
    Taps teo; teo.n = 2;
    teo.t[0] = 1; teo.di[0] = -1; teo.dj[0] = 0;
    teo.t[1] = 7; teo.di[1] = 0;  teo.dj[1] = 0;
    Taps toe; toe.n = 2;
    toe.t[0] = 3; toe.di[0] = 0; toe.dj[0] = -1;
    toe.t[1] = 5; toe.di[1] = 0; toe.dj[1] = 0;
    Taps too; too.n = 1;
    too.t[0] = 4; too.di[0] = 0; too.dj[0] = 0;

    dim3 gT(4, 8, BATCH);
    k_gemm<0><<<gT, 256, SMEM>>>(x, conv1_w, tee, 0, 0, nullptr, nullptr, nullptr, nullptr);
    k_gemm<0><<<gT, 256, SMEM>>>(x, conv1_w, teo, 0, 1, nullptr, nullptr, nullptr, nullptr);
    k_gemm<0><<<gT, 256, SMEM>>>(x, conv1_w, toe, 1, 0, nullptr, nullptr, nullptr, nullptr);
    k_gemm<0><<<gT, 256, SMEM>>>(x, conv1_w, too, 1, 1, nullptr, nullptr, nullptr, nullptr);

    k_blur<<<dim3(WOUT, HOUT, BATCH), 128>>>(noise1, sn1, bias1);

    Taps t2; t2.n = 9;
    for (int dh = 0; dh < 3; dh++)
        for (int dw = 0; dw < 3; dw++) {
            int i = dh * 3 + dw;
            t2.t[i] = i; t2.di[i] = dh - 1; t2.dj[i] = dw - 1;
        }
    k_gemm<1><<<dim3(4, 32, BATCH), 256, SMEM>>>(nullptr, conv2_w, t2, 0, 0, noise2, sn2, bias2, xpart);

    k_rgb<<<dim3(HOUT * WOUT / 8, BATCH), 256>>>(xpart, convr_w, biasr, rgbpart);
}

// round 8
// speedup vs baseline: 2.2312x; 1.7458x over previous
#include <cuda_runtime.h>
#include <cstdint>

#define BATCH 16
#define HIN 32
#define WIN 32
#define CH 512
#define HOUT 64
#define WOUT 64

__device__ float g_s1[BATCH][CH];
__device__ float g_s2[BATCH][CH];
__device__ float g_sr[BATCH][CH];
__device__ float g_d1[BATCH][CH];
__device__ float g_d2[BATCH][CH];
__device__ float g_wsq1[CH * CH];
__device__ float g_wsq2[CH * CH];
__device__ float g_y[(size_t)BATCH * HOUT * WOUT * CH];
__device__ float g_x1[(size_t)BATCH * HOUT * WOUT * CH];

__device__ __forceinline__ float lrelu(float v) { return v > 0.f ? v : 0.2f * v; }

__device__ __forceinline__ uint32_t smem_u32(const void* p) {
    uint32_t a;
    asm("{ .reg .u64 t; cvta.to.shared.u64 t, %1; cvt.u32.u64 %0, t; }" : "=r"(a) : "l"(p));
    return a;
}
// pack two floats to bf16x2: low half = f0 (lower k index), high half = f1
__device__ __forceinline__ uint32_t pack_bf16(float f0, float f1) {
    uint32_t r;
    asm("cvt.rn.bf16x2.f32 %0, %1, %2;" : "=r"(r) : "f"(f1), "f"(f0));
    return r;
}
__device__ __forceinline__ float bf_lo(uint32_t p) { return __uint_as_float(p << 16); }
__device__ __forceinline__ float bf_hi(uint32_t p) { return __uint_as_float(p & 0xffff0000u); }
// m16n8k16 bf16 MMA, fp32 accum
__device__ __forceinline__ void mma16(float* d, const uint32_t* a, uint32_t b0, uint32_t b1) {
    asm volatile(
        "mma.sync.aligned.m16n8k16.row.col.f32.bf16.bf16.f32 "
        "{%0,%1,%2,%3},{%4,%5,%6,%7},{%8,%9},{%0,%1,%2,%3};"
        : "+f"(d[0]), "+f"(d[1]), "+f"(d[2]), "+f"(d[3])
        : "r"(a[0]), "r"(a[1]), "r"(a[2]), "r"(a[3]), "r"(b0), "r"(b1));
}
__device__ __forceinline__ void lds128(uint32_t* r, uint32_t a) {
    asm volatile("ld.shared.v4.b32 {%0,%1,%2,%3},[%4];"
                 : "=r"(r[0]), "=r"(r[1]), "=r"(r[2]), "=r"(r[3]) : "r"(a));
}
__device__ __forceinline__ void sts32(uint32_t a, uint32_t v) {
    asm volatile("st.shared.b32 [%0],%1;" :: "r"(a), "r"(v) : "memory");
}

// ---------------- fused styles (3 FC layers), grid (BATCH, 3) -------------------
__global__ void k_styles(const float* __restrict__ w,
                         const float* __restrict__ f1w, const float* __restrict__ f1b,
                         const float* __restrict__ f2w, const float* __restrict__ f2b,
                         const float* __restrict__ frw, const float* __restrict__ frb) {
    int b = blockIdx.x, which = blockIdx.y, co = threadIdx.x;
    const float* fw = which == 0 ? f1w : (which == 1 ? f2w : frw);
    const float* fb = which == 0 ? f1b : (which == 1 ? f2b : frb);
    __shared__ float sw_[CH];
    sw_[co] = w[b * CH + co];
    __syncthreads();
    float acc = 0.f;
#pragma unroll 4
    for (int ci = 0; ci < CH; ci++) acc = fmaf(sw_[ci], fw[ci * CH + co], acc);
    float v = acc * 0.044194173824159216f + fb[co];
    if (which == 0) g_s1[b][co] = v;
    else if (which == 1) g_s2[b][co] = v;
    else g_sr[b][co] = v;
}

__global__ void k_wsq(const float* __restrict__ w1, const float* __restrict__ w2) {
    int idx = blockIdx.x * 256 + threadIdx.x;
    const float ws2 = 1.0f / 4608.0f;
    float a1 = 0.f, a2 = 0.f;
#pragma unroll
    for (int t = 0; t < 9; t++) {
        float v1 = w1[(size_t)t * CH * CH + idx];
        a1 = fmaf(v1, v1, a1);
        float v2 = w2[(size_t)t * CH * CH + idx];
        a2 = fmaf(v2, v2, a2);
    }
    g_wsq1[idx] = a1 * ws2;
    g_wsq2[idx] = a2 * ws2;
}

// grid (BATCH, 2)
__global__ void k_demod() {
    int b = blockIdx.x, which = blockIdx.y, co = threadIdx.x;
    __shared__ float ss[CH];
    float s = which ? g_s2[b][co] : g_s1[b][co];
    ss[co] = s * s;
    __syncthreads();
    const float* wsq = which ? g_wsq2 : g_wsq1;
    float acc = 0.f;
#pragma unroll 4
    for (int ci = 0; ci < CH; ci++) acc = fmaf(ss[ci], wsq[ci * CH + co], acc);
    float d = rsqrtf(acc + 1e-8f);
    if (which) g_d2[b][co] = d;
    else g_d1[b][co] = d;
}

struct Taps { int n; int t[9]; int di[9]; int dj[9]; };

// Implicit-GEMM conv, bf16 3-term split (hh + hl + lh) via mma.sync m16n8k16.
// Fragments pre-split & pre-arranged in SMEM by staging threads; mainloop = LDS.128 + MMA.
// CTA: M=128 pixels x N=128 couts; 8 warps (4 along M x 2 along N); single buffer.
// SMEM layout (uint32): AH[16 blk][132], AL[16 blk][132], BHL[32 blk][132]
//   A block id = kc*8 + (row>>4); in-block idx = lane*4 + v,
//     lane = ((row&7)<<2) | ((k>>1)&3), v = ((row>>3)&1) | (((k>>3)&1)<<1)
//   B block id = kc*16 + (n>>3); in-block idx = lane*4 + slot,
//     lane = ((n&7)<<2) | ((k>>1)&3), slot = ((k>>3)&1) for hi, 2+same for lo
#define BLK 132
#define GSMEM ((16 + 16 + 32) * BLK * 4)

template <int MODE>
__global__ __launch_bounds__(256, 2) void k_gemm(
    const float* __restrict__ xin, const float* __restrict__ cw, Taps taps,
    int uo, int vo, const float* __restrict__ noise, const float* __restrict__ snp,
    const float* __restrict__ biasp, float* __restrict__ outp) {
    constexpr int HI = MODE ? HOUT : HIN;
    constexpr int WI = MODE ? WOUT : WIN;
    extern __shared__ uint32_t smu[];
    __shared__ float s_mul[CH];
    __shared__ float s_dv[128], s_sn[128], s_bb[128];

    const int tid = threadIdx.x, lane = tid & 31, wid = tid >> 5;
    const int wm = wid & 3, wn = wid >> 2;
    const int b = blockIdx.z, co0 = blockIdx.x * 128;
    int pb, qb;
    if (MODE) { pb = (blockIdx.y >> 2) * 8; qb = (blockIdx.y & 3) * 16; }
    else      { pb = (blockIdx.y >> 1) * 8; qb = (blockIdx.y & 1) * 16; }

    const float* src = MODE ? &g_x1[0] : xin;
    const float* sty = MODE ? g_s2[b] : g_s1[b];
    const float wscale = 0.014731391274719742f;  // 1/sqrt(9*512)
    for (int i = tid; i < CH; i += 256) s_mul[i] = sty[i] * wscale;
    if (MODE && tid < 128) {
        s_dv[tid] = g_d2[b][co0 + tid];
        s_sn[tid] = snp[co0 + tid];
        s_bb[tid] = biasp[co0 + tid];
    }

    const uint32_t AH = smem_u32(smu);
    const uint32_t AL = AH + 16 * BLK * 4;
    const uint32_t BH = AH + 32 * BLK * 4;

    // A staging: thread -> pixel row (0..127) and k-half (0 or 16)
    const int arow = tid >> 1, akhalf = (tid & 1) * 16;
    const int arg = arow >> 4, ar8 = (arow >> 3) & 1, alb = (arow & 7) << 2;
    const int apr = arow >> 4, apc = arow & 15;
    const int akc = akhalf >> 4;
    const uint32_t abase = AH + (uint32_t)((akc * 8 + arg) * BLK) * 4;
    const uint32_t abaseL = AL + (uint32_t)((akc * 8 + arg) * BLK) * 4;
    // B staging: thread -> k-pair (0..15) and 8-wide n segment
    const int bp = tid >> 4, bn0 = (tid & 15) * 8;
    const int bkc = bp >> 3, bpl = bp & 7, bc = bpl & 3, br = bpl >> 2;
    const uint32_t bbase = BH + (uint32_t)((bkc * 16 + (tid & 15)) * BLK) * 4;

    float acc[2][8][4];
#pragma unroll
    for (int i = 0; i < 2; i++)
#pragma unroll
        for (int j = 0; j < 8; j++)
#pragma unroll
            for (int k = 0; k < 4; k++) acc[i][j][k] = 0.f;

    const int nkb = taps.n * 16;
    __syncthreads();

    for (int kb = 0; kb < nkb; kb++) {
        const int tp = kb >> 4, ci0 = (kb & 15) << 5;
        const int di = taps.di[tp], dj = taps.dj[tp], t = taps.t[tp];
        // ---- stage A (style-modulated, bf16 hi/lo, fragment order)
        {
            int gp = pb + apr + di, gq = qb + apc + dj;
            float4 v0, v1, v2, v3;
            if ((unsigned)gp < (unsigned)HI && (unsigned)gq < (unsigned)WI) {
                const float* s = &src[(((size_t)b * HI + gp) * WI + gq) * CH + ci0 + akhalf];
                v0 = *(const float4*)(s);
                v1 = *(const float4*)(s + 4);
                v2 = *(const float4*)(s + 8);
                v3 = *(const float4*)(s + 12);
            } else {
                v0 = v1 = v2 = v3 = make_float4(0.f, 0.f, 0.f, 0.f);
            }
            const float* mul = &s_mul[ci0 + akhalf];
#define APAIR(J, F0, F1)                                                    \
    {                                                                       \
        float f0_ = (F0) * mul[2 * (J)];                                    \
        float f1_ = (F1) * mul[2 * (J) + 1];                                \
        uint32_t h_ = pack_bf16(f0_, f1_);                                  \
        uint32_t l_ = pack_bf16(f0_ - bf_lo(h_), f1_ - bf_hi(h_));          \
        uint32_t off_ = (((alb | ((J) & 3)) << 2) + (ar8 | (((J) >> 2) << 1))) << 2; \
        sts32(abase + off_, h_);                                            \
        sts32(abaseL + off_, l_);                                           \
    }
            APAIR(0, v0.x, v0.y) APAIR(1, v0.z, v0.w)
            APAIR(2, v1.x, v1.y) APAIR(3, v1.z, v1.w)
            APAIR(4, v2.x, v2.y) APAIR(5, v2.z, v2.w)
            APAIR(6, v3.x, v3.y) APAIR(7, v3.z, v3.w)
#undef APAIR
        }
        // ---- stage B (raw weights, bf16 hi/lo, fragment order)
        {
            const float* w0 = cw + (size_t)t * CH * CH + (size_t)(ci0 + 2 * bp) * CH + co0 + bn0;
            float4 r0a = *(const float4*)(w0);
            float4 r0b = *(const float4*)(w0 + 4);
            float4 r1a = *(const float4*)(w0 + CH);
            float4 r1b = *(const float4*)(w0 + CH + 4);
#define BPAIR(J, F0, F1)                                                    \
    {                                                                       \
        uint32_t h_ = pack_bf16((F0), (F1));                                \
        uint32_t l_ = pack_bf16((F0) - bf_lo(h_), (F1) - bf_hi(h_));        \
        uint32_t off_ = (((((J) << 2) | bc) << 2) + br) << 2;               \
        sts32(bbase + off_, h_);                                            \
        sts32(bbase + off_ + 8, l_);                                        \
    }
            BPAIR(0, r0a.x, r1a.x) BPAIR(1, r0a.y, r1a.y)
            BPAIR(2, r0a.z, r1a.z) BPAIR(3, r0a.w, r1a.w)
            BPAIR(4, r0b.x, r1b.x) BPAIR(5, r0b.y, r1b.y)
            BPAIR(6, r0b.z, r1b.z) BPAIR(7, r0b.w, r1b.w)
#undef BPAIR
        }
        __syncthreads();
        // ---- MMA over the staged 32-k block
#pragma unroll
        for (int kc = 0; kc < 2; kc++) {
            uint32_t ah[2][4], al[2][4];
#pragma unroll
            for (int mt = 0; mt < 2; mt++) {
                uint32_t ba = (uint32_t)((kc * 8 + (wm << 1) + mt) * BLK) * 4 + lane * 16;
                lds128(ah[mt], AH + ba);
                lds128(al[mt], AL + ba);
            }
#pragma unroll
            for (int nt = 0; nt < 8; nt++) {
                uint32_t bbf[4];
                lds128(bbf, BH + (uint32_t)((kc * 16 + (wn << 3) + nt) * BLK) * 4 + lane * 16);
#pragma unroll
                for (int mt = 0; mt < 2; mt++) {
                    mma16(acc[mt][nt], ah[mt], bbf[0], bbf[1]);
                    mma16(acc[mt][nt], ah[mt], bbf[2], bbf[3]);
                    mma16(acc[mt][nt], al[mt], bbf[0], bbf[1]);
                }
            }
        }
        __syncthreads();
    }

    // ---- epilogue: D frag c0,c1 at (row=lane>>2, col=2*(lane&3)); c2,c3 at row+8
    const int r0 = wm * 32 + (lane >> 2);
    const int cb = wn * 64 + (lane & 3) * 2;
#pragma unroll
    for (int mt = 0; mt < 2; mt++)
#pragma unroll
        for (int half = 0; half < 2; half++) {
            int m = r0 + mt * 16 + half * 8;
            int pr = m >> 4, pc = m & 15;
            int p, q;
            if (MODE) { p = pb + pr; q = qb + pc; }
            else      { p = 2 * (pb + pr) + uo; q = 2 * (qb + pc) + vo; }
            size_t base = (((size_t)b * HOUT + p) * WOUT + q) * CH + co0;
            float nz = MODE ? noise[((size_t)b * HOUT + p) * WOUT + q] : 0.f;
#pragma unroll
            for (int nt = 0; nt < 8; nt++) {
                int col = cb + nt * 8;
                float v0 = acc[mt][nt][half * 2 + 0];
                float v1 = acc[mt][nt][half * 2 + 1];
                float2 o;
                if (MODE) {
                    o.x = lrelu(v0 * s_dv[col] + s_sn[col] * nz + s_bb[col]);
                    o.y = lrelu(v1 * s_dv[col + 1] + s_sn[col + 1] * nz + s_bb[col + 1]);
                    *(float2*)&outp[base + col] = o;
                } else {
                    o.x = v0; o.y = v1;
                    *(float2*)&g_y[base + col] = o;
                }
            }
        }
}

__global__ void k_blur(const float* __restrict__ noise1, const float* __restrict__ sn1,
                       const float* __restrict__ bias1) {
    int q = blockIdx.x, p = blockIdx.y, b = blockIdx.z;
    int c = threadIdx.x << 2;
    const float fw[4] = {1.f, 3.f, 3.f, 1.f};
    float4 acc = make_float4(0.f, 0.f, 0.f, 0.f);
#pragma unroll
    for (int eh = 0; eh < 4; eh++) {
        int pp = p + eh - 1;
        if ((unsigned)pp >= HOUT) continue;
        float4 row = make_float4(0.f, 0.f, 0.f, 0.f);
#pragma unroll
        for (int ew = 0; ew < 4; ew++) {
            int qq = q + ew - 1;
            if ((unsigned)qq >= WOUT) continue;
            float4 v = *(const float4*)&g_y[(((size_t)b * HOUT + pp) * WOUT + qq) * CH + c];
            row.x += v.x * fw[ew]; row.y += v.y * fw[ew];
            row.z += v.z * fw[ew]; row.w += v.w * fw[ew];
        }
        acc.x += row.x * fw[eh]; acc.y += row.y * fw[eh];
        acc.z += row.z * fw[eh]; acc.w += row.w * fw[eh];
    }
    const float inv16 = 0.0625f;
    float4 dv = *(const float4*)&g_d1[b][c];
    float4 sn = *(const float4*)&sn1[c];
    float4 bb = *(const float4*)&bias1[c];
    float nz = noise1[((size_t)b * HOUT + p) * WOUT + q];
    float4 o;
    o.x = lrelu(acc.x * inv16 * dv.x + sn.x * nz + bb.x);
    o.y = lrelu(acc.y * inv16 * dv.y + sn.y * nz + bb.y);
    o.z = lrelu(acc.z * inv16 * dv.z + sn.z * nz + bb.z);
    o.w = lrelu(acc.w * inv16 * dv.w + sn.w * nz + bb.w);
    *(float4*)&g_x1[(((size_t)b * HOUT + p) * WOUT + q) * CH + c] = o;
}

__global__ void k_rgb(const float* __restrict__ x2, const float* __restrict__ wr,
                      const float* __restrict__ br, float* __restrict__ rgb) {
    int b = blockIdx.y, tid = threadIdx.x;
    __shared__ float wc[CH * 3];
    const float wscale = 0.044194173824159216f;
    for (int k = tid; k < CH * 3; k += 256) {
        int ci = k / 3;
        wc[k] = g_sr[b][ci] * wscale * wr[k];
    }
    __syncthreads();
    int warp = tid >> 5, lane = tid & 31;
    int pix = blockIdx.x * 8 + warp;
    const float* xp = x2 + ((size_t)b * HOUT * WOUT + pix) * CH;
    float a0 = 0.f, a1 = 0.f, a2 = 0.f;
    for (int ci = lane; ci < CH; ci += 32) {
        float v = xp[ci];
        a0 = fmaf(v, wc[ci * 3 + 0], a0);
        a1 = fmaf(v, wc[ci * 3 + 1], a1);
        a2 = fmaf(v, wc[ci * 3 + 2], a2);
    }
#pragma unroll
    for (int o = 16; o; o >>= 1) {
        a0 += __shfl_xor_sync(0xffffffffu, a0, o);
        a1 += __shfl_xor_sync(0xffffffffu, a1, o);
        a2 += __shfl_xor_sync(0xffffffffu, a2, o);
    }
    if (lane == 0) {
        size_t base = ((size_t)b * HOUT * WOUT + pix) * 3;
        rgb[base + 0] = lrelu(a0 + br[0]);
        rgb[base + 1] = lrelu(a1 + br[1]);
        rgb[base + 2] = lrelu(a2 + br[2]);
    }
}

extern "C" void kernel_launch(void* const* d_in, const int* in_sizes, int n_in,
                              void* d_out, int out_size) {
    const float* x       = (const float*)d_in[0];
    const float* w       = (const float*)d_in[1];
    const float* noise1  = (const float*)d_in[2];
    const float* noise2  = (const float*)d_in[3];
    const float* fcl1_w  = (const float*)d_in[4];
    const float* fcl1_b  = (const float*)d_in[5];
    const float* conv1_w = (const float*)d_in[6];
    const float* sn1     = (const float*)d_in[7];
    const float* bias1   = (const float*)d_in[8];
    const float* fcl2_w  = (const float*)d_in[9];
    const float* fcl2_b  = (const float*)d_in[10];
    const float* conv2_w = (const float*)d_in[11];
    const float* sn2     = (const float*)d_in[12];
    const float* bias2   = (const float*)d_in[13];
    const float* fclr_w  = (const float*)d_in[14];
    const float* fclr_b  = (const float*)d_in[15];
    const float* convr_w = (const float*)d_in[16];
    const float* biasr   = (const float*)d_in[17];
    float* out = (float*)d_out;
    float* xpart = out;
    float* rgbpart = out + (size_t)BATCH * HOUT * WOUT * CH;

    k_styles<<<dim3(BATCH, 3), 512>>>(w, fcl1_w, fcl1_b, fcl2_w, fcl2_b, fclr_w, fclr_b);
    k_wsq<<<(CH * CH) / 256, 256>>>(conv1_w, conv2_w);
    k_demod<<<dim3(BATCH, 2), 512>>>();

    // convT parity classes (validated in R2): y[2i+u,2j+v] = sum_t w[t]*x[i+di, j+dj]
    Taps tee; tee.n = 4;
    tee.t[0] = 0; tee.di[0] = -1; tee.dj[0] = -1;
    tee.t[1] = 2; tee.di[1] = -1; tee.dj[1] = 0;
    tee.t[2] = 6; tee.di[2] = 0;  tee.dj[2] = -1;
    tee.t[3] = 8; tee.di[3] = 0;  tee.dj[3] = 0;
    Taps teo; teo.n = 2;
    teo.t[0] = 1; teo.di[0] = -1; teo.dj[0] = 0;
    teo.t[1] = 7; teo.di[1] = 0;  teo.dj[1] = 0;
    Taps toe; toe.n = 2;
    toe.t[0] = 3; toe.di[0] = 0; toe.dj[0] = -1;
    toe.t[1] = 5; toe.di[1] = 0; toe.dj[1] = 0;
    Taps too; too.n = 1;
    too.t[0] = 4; too.di[0] = 0; too.dj[0] = 0;

    dim3 gT(4, 8, BATCH);
    k_gemm<0><<<gT, 256, GSMEM>>>(x, conv1_w, tee, 0, 0, nullptr, nullptr, nullptr, nullptr);
    k_gemm<0><<<gT, 256, GSMEM>>>(x, conv1_w, teo, 0, 1, nullptr, nullptr, nullptr, nullptr);
    k_gemm<0><<<gT, 256, GSMEM>>>(x, conv1_w, toe, 1, 0, nullptr, nullptr, nullptr, nullptr);
    k_gemm<0><<<gT, 256, GSMEM>>>(x, conv1_w, too, 1, 1, nullptr, nullptr, nullptr, nullptr);

    k_blur<<<dim3(WOUT, HOUT, BATCH), 128>>>(noise1, sn1, bias1);

    Taps t2; t2.n = 9;
    for (int dh = 0; dh < 3; dh++)
        for (int dw = 0; dw < 3; dw++) {
            int i = dh * 3 + dw;
            t2.t[i] = i; t2.di[i] = dh - 1; t2.dj[i] = dw - 1;
        }
    k_gemm<1><<<dim3(4, 32, BATCH), 256, GSMEM>>>(nullptr, conv2_w, t2, 0, 0, noise2, sn2, bias2, xpart);

    k_rgb<<<dim3(HOUT * WOUT / 8, BATCH), 256>>>(xpart, convr_w, biasr, rgbpart);
}

// round 10
// speedup vs baseline: 2.4956x; 1.1185x over previous
#include <cuda_runtime.h>
#include <cstdint>

#define BATCH 16
#define HIN 32
#define WIN 32
#define CH 512
#define HOUT 64
#define WOUT 64
#define WSCALE 0.014731391274719742f

__device__ float g_s1[BATCH][CH];
__device__ float g_s2[BATCH][CH];
__device__ float g_sr[BATCH][CH];
__device__ float g_d1[BATCH][CH];
__device__ float g_d2[BATCH][CH];
__device__ float g_wsq1[CH * CH];
__device__ float g_wsq2[CH * CH];
__device__ float g_y[(size_t)BATCH * HOUT * WOUT * CH];
// pre-split bf16 activations (u32 = bf16x2 channel pair), NHWC/2
__device__ uint32_t g_xh[(size_t)BATCH * HIN * WIN * 256];
__device__ uint32_t g_xl[(size_t)BATCH * HIN * WIN * 256];
__device__ uint32_t g_x1h[(size_t)BATCH * HOUT * WOUT * 256];
__device__ uint32_t g_x1l[(size_t)BATCH * HOUT * WOUT * 256];
// pre-split weights in fragment order: [tap][cob4][kci16][blk32][128 u32]
#define WSPN (9 * 4 * 16 * 32 * 128)
__device__ uint32_t g_wspA[WSPN];
__device__ uint32_t g_wspB[WSPN];

__device__ __forceinline__ float lrelu(float v) { return v > 0.f ? v : 0.2f * v; }

__device__ __forceinline__ uint32_t smem_u32(const void* p) {
    uint32_t a;
    asm("{ .reg .u64 t; cvta.to.shared.u64 t, %1; cvt.u32.u64 %0, t; }" : "=r"(a) : "l"(p));
    return a;
}
__device__ __forceinline__ uint32_t pack_bf16(float f0, float f1) {
    uint32_t r;
    asm("cvt.rn.bf16x2.f32 %0, %1, %2;" : "=r"(r) : "f"(f1), "f"(f0));
    return r;
}
__device__ __forceinline__ float bf_lo(uint32_t p) { return __uint_as_float(p << 16); }
__device__ __forceinline__ float bf_hi(uint32_t p) { return __uint_as_float(p & 0xffff0000u); }
__device__ __forceinline__ void mma16(float* d, const uint32_t* a, uint32_t b0, uint32_t b1) {
    asm volatile(
        "mma.sync.aligned.m16n8k16.row.col.f32.bf16.bf16.f32 "
        "{%0,%1,%2,%3},{%4,%5,%6,%7},{%8,%9},{%0,%1,%2,%3};"
        : "+f"(d[0]), "+f"(d[1]), "+f"(d[2]), "+f"(d[3])
        : "r"(a[0]), "r"(a[1]), "r"(a[2]), "r"(a[3]), "r"(b0), "r"(b1));
}
__device__ __forceinline__ void lds128(uint32_t* r, uint32_t a) {
    asm volatile("ld.shared.v4.b32 {%0,%1,%2,%3},[%4];"
                 : "=r"(r[0]), "=r"(r[1]), "=r"(r[2]), "=r"(r[3]) : "r"(a));
}
__device__ __forceinline__ void sts32(uint32_t a, uint32_t v) {
    asm volatile("st.shared.b32 [%0],%1;" :: "r"(a), "r"(v) : "memory");
}
__device__ __forceinline__ void cpa16(uint32_t dst, const uint32_t* src) {
    asm volatile("cp.async.cg.shared.global [%0], [%1], 16;"
                 :: "r"(dst), "l"(src) : "memory");
}
#define CP_COMMIT() asm volatile("cp.async.commit_group;" ::: "memory")
#define CP_WAIT0() asm volatile("cp.async.wait_group 0;" ::: "memory")

// ---------------- styles (3 FC layers), grid (BATCH, 3) -------------------------
__global__ void k_styles(const float* __restrict__ w,
                         const float* __restrict__ f1w, const float* __restrict__ f1b,
                         const float* __restrict__ f2w, const float* __restrict__ f2b,
                         const float* __restrict__ frw, const float* __restrict__ frb) {
    int b = blockIdx.x, which = blockIdx.y, co = threadIdx.x;
    const float* fw = which == 0 ? f1w : (which == 1 ? f2w : frw);
    const float* fb = which == 0 ? f1b : (which == 1 ? f2b : frb);
    __shared__ float sw_[CH];
    sw_[co] = w[b * CH + co];
    __syncthreads();
    float acc = 0.f;
#pragma unroll 4
    for (int ci = 0; ci < CH; ci++) acc = fmaf(sw_[ci], fw[ci * CH + co], acc);
    float v = acc * 0.044194173824159216f + fb[co];
    if (which == 0) g_s1[b][co] = v;
    else if (which == 1) g_s2[b][co] = v;
    else g_sr[b][co] = v;
}

__global__ void k_wsq(const float* __restrict__ w1, const float* __restrict__ w2) {
    int idx = blockIdx.x * 256 + threadIdx.x;
    const float ws2 = 1.0f / 4608.0f;
    float a1 = 0.f, a2 = 0.f;
#pragma unroll
    for (int t = 0; t < 9; t++) {
        float v1 = w1[(size_t)t * CH * CH + idx];
        a1 = fmaf(v1, v1, a1);
        float v2 = w2[(size_t)t * CH * CH + idx];
        a2 = fmaf(v2, v2, a2);
    }
    g_wsq1[idx] = a1 * ws2;
    g_wsq2[idx] = a2 * ws2;
}

__global__ void k_demod() {
    int b = blockIdx.x, which = blockIdx.y, co = threadIdx.x;
    __shared__ float ss[CH];
    float s = which ? g_s2[b][co] : g_s1[b][co];
    ss[co] = s * s;
    __syncthreads();
    const float* wsq = which ? g_wsq2 : g_wsq1;
    float acc = 0.f;
#pragma unroll 4
    for (int ci = 0; ci < CH; ci++) acc = fmaf(ss[ci], wsq[ci * CH + co], acc);
    float d = rsqrtf(acc + 1e-8f);
    if (which) g_d2[b][co] = d;
    else g_d1[b][co] = d;
}

// ---------------- weight pre-split into fragment order, grid 4608 ---------------
// FIX vs R9: select destination INSIDE device code (host code must not pass a
// __device__ array symbol as a kernel argument — that address is invalid).
__global__ void k_wsplit(const float* __restrict__ cw, int which) {
    uint32_t* __restrict__ out = which ? g_wspB : g_wspA;
    int bx = blockIdx.x;                        // 576 units * 8 parts
    int u = bx >> 3, part = bx & 7;
    int tap = u >> 6, r = u & 63, cob = r >> 4, kci = r & 15;
    int within = part * 256 + threadIdx.x;      // 0..2047
    int blk = within >> 6, s = within & 63, lane = s >> 1, br = s & 1;
    int n = (blk & 15) * 8 + (lane >> 2);
    int kc = blk >> 4;
    int kk = kc * 16 + ((lane & 3) << 1) + (br << 3);
    int ci = kci * 32 + kk, co = cob * 128 + n;
    float w0 = cw[((size_t)tap * CH + ci) * CH + co];
    float w1 = cw[((size_t)tap * CH + ci + 1) * CH + co];
    uint32_t h = pack_bf16(w0, w1);
    uint32_t l = pack_bf16(w0 - bf_lo(h), w1 - bf_hi(h));
    size_t base = ((((size_t)tap * 4 + cob) * 16 + kci) * 32 + blk) * 128 + lane * 4 + br;
    out[base] = h;
    out[base + 2] = l;
}

// ---------------- pre-split x * s1 * wscale, grid 16384 -------------------------
__global__ void k_presplit_x(const float* __restrict__ x) {
    int id = blockIdx.x * 256 + threadIdx.x;    // < 16*32*32*256
    int p2 = id & 255;
    int pix = id >> 8;
    int b = pix >> 10;
    int ci = p2 * 2;
    float v0 = x[(size_t)pix * CH + ci] * (g_s1[b][ci] * WSCALE);
    float v1 = x[(size_t)pix * CH + ci + 1] * (g_s1[b][ci + 1] * WSCALE);
    uint32_t h = pack_bf16(v0, v1);
    g_xh[id] = h;
    g_xl[id] = pack_bf16(v0 - bf_lo(h), v1 - bf_hi(h));
}

struct Taps { int n; int t[9]; int di[9]; int dj[9]; };

// Implicit-GEMM conv, bf16 3-term split via mma.sync m16n8k16. All operands
// pre-split; B staged by cp.async from fragment-ordered global, A by LDG+STS reorder.
#define BLK 132
#define GSMEM ((16 + 16 + 32) * BLK * 4)

template <int MODE>
__global__ __launch_bounds__(256, 2) void k_gemm(
    Taps taps, int uo, int vo, const float* __restrict__ noise,
    const float* __restrict__ snp, const float* __restrict__ biasp,
    float* __restrict__ outp) {
    constexpr int HI = MODE ? HOUT : HIN;
    constexpr int WI = MODE ? WOUT : WIN;
    extern __shared__ uint32_t smu[];
    __shared__ float s_dv[128], s_sn[128], s_bb[128];

    const int tid = threadIdx.x, lane = tid & 31, wid = tid >> 5;
    const int wm = wid & 3, wn = wid >> 2;
    const int b = blockIdx.z, co0 = blockIdx.x * 128;
    int pb, qb;
    if (MODE) { pb = (blockIdx.y >> 2) * 8; qb = (blockIdx.y & 3) * 16; }
    else      { pb = (blockIdx.y >> 1) * 8; qb = (blockIdx.y & 1) * 16; }

    const uint32_t* axh = MODE ? g_x1h : g_xh;
    const uint32_t* axl = MODE ? g_x1l : g_xl;
    const uint32_t* wsp = MODE ? g_wspB : g_wspA;

    if (MODE && tid < 128) {
        s_dv[tid] = g_d2[b][co0 + tid];
        s_sn[tid] = snp[co0 + tid];
        s_bb[tid] = biasp[co0 + tid];
    }

    const uint32_t AH = smem_u32(smu);
    const uint32_t AL = AH + 16 * BLK * 4;
    const uint32_t BH = AH + 32 * BLK * 4;

    // A staging coords
    const int arow = tid >> 1, akhalf8 = (tid & 1) * 8;  // 8 u32 (=16 ch) half
    const int arg = arow >> 4, ar8 = (arow >> 3) & 1, alb = (arow & 7) << 2;
    const int apr = arow >> 4, apc = arow & 15;
    const uint32_t abase = AH + (uint32_t)(((tid & 1) * 8 + arg) * BLK) * 4;
    const uint32_t abaseL = AL + (uint32_t)(((tid & 1) * 8 + arg) * BLK) * 4;

    float acc[2][8][4];
#pragma unroll
    for (int i = 0; i < 2; i++)
#pragma unroll
        for (int j = 0; j < 8; j++)
#pragma unroll
            for (int k = 0; k < 4; k++) acc[i][j][k] = 0.f;

    const int nkb = taps.n * 16;
    __syncthreads();

    for (int kb = 0; kb < nkb; kb++) {
        const int tp = kb >> 4, kci = kb & 15;
        const int di = taps.di[tp], dj = taps.dj[tp], t = taps.t[tp];
        // ---- B: cp.async from fragment-ordered pre-split weights
        {
            const uint32_t* wb = wsp + ((((size_t)t * 4 + blockIdx.x) * 16 + kci) * 32) * 128;
#pragma unroll
            for (int c = 0; c < 4; c++) {
                int l16 = tid + c * 256;
                int blk = l16 >> 5, in16 = l16 & 31;
                cpa16(BH + (uint32_t)(blk * (BLK * 4) + in16 * 16), wb + blk * 128 + in16 * 4);
            }
            CP_COMMIT();
        }
        // ---- A: pre-split bf16 pairs -> fragment-order STS (no math)
        {
            int gp = pb + apr + di, gq = qb + apc + dj;
            uint4 h0, h1, l0, l1;
            if ((unsigned)gp < (unsigned)HI && (unsigned)gq < (unsigned)WI) {
                size_t o = ((size_t)(b * HI + gp) * WI + gq) * 256 + kci * 16 + akhalf8;
                h0 = *(const uint4*)(axh + o);
                h1 = *(const uint4*)(axh + o + 4);
                l0 = *(const uint4*)(axl + o);
                l1 = *(const uint4*)(axl + o + 4);
            } else {
                h0 = h1 = l0 = l1 = make_uint4(0u, 0u, 0u, 0u);
            }
#define APUT(J, HV, LV)                                                              \
    {                                                                                \
        uint32_t off_ = (((alb | ((J) & 3)) << 2) + (ar8 | (((J) >> 2) << 1))) << 2; \
        sts32(abase + off_, (HV));                                                   \
        sts32(abaseL + off_, (LV));                                                  \
    }
            APUT(0, h0.x, l0.x) APUT(1, h0.y, l0.y) APUT(2, h0.z, l0.z) APUT(3, h0.w, l0.w)
            APUT(4, h1.x, l1.x) APUT(5, h1.y, l1.y) APUT(6, h1.z, l1.z) APUT(7, h1.w, l1.w)
#undef APUT
        }
        CP_WAIT0();
        __syncthreads();
        // ---- MMA over staged 32-k block
#pragma unroll
        for (int kc = 0; kc < 2; kc++) {
            uint32_t ah[2][4], al[2][4];
#pragma unroll
            for (int mt = 0; mt < 2; mt++) {
                uint32_t ba = (uint32_t)((kc * 8 + (wm << 1) + mt) * BLK) * 4 + lane * 16;
                lds128(ah[mt], AH + ba);
                lds128(al[mt], AL + ba);
            }
#pragma unroll
            for (int nt = 0; nt < 8; nt++) {
                uint32_t bbf[4];
                lds128(bbf, BH + (uint32_t)((kc * 16 + (wn << 3) + nt) * BLK) * 4 + lane * 16);
#pragma unroll
                for (int mt = 0; mt < 2; mt++) {
                    mma16(acc[mt][nt], ah[mt], bbf[0], bbf[1]);
                    mma16(acc[mt][nt], ah[mt], bbf[2], bbf[3]);
                    mma16(acc[mt][nt], al[mt], bbf[0], bbf[1]);
                }
            }
        }
        __syncthreads();
    }

    // ---- epilogue
    const int r0 = wm * 32 + (lane >> 2);
    const int cb = wn * 64 + (lane & 3) * 2;
#pragma unroll
    for (int mt = 0; mt < 2; mt++)
#pragma unroll
        for (int half = 0; half < 2; half++) {
            int m = r0 + mt * 16 + half * 8;
            int pr = m >> 4, pc = m & 15;
            int p, q;
            if (MODE) { p = pb + pr; q = qb + pc; }
            else      { p = 2 * (pb + pr) + uo; q = 2 * (qb + pc) + vo; }
            size_t base = (((size_t)b * HOUT + p) * WOUT + q) * CH + co0;
            float nz = MODE ? noise[((size_t)b * HOUT + p) * WOUT + q] : 0.f;
#pragma unroll
            for (int nt = 0; nt < 8; nt++) {
                int col = cb + nt * 8;
                float v0 = acc[mt][nt][half * 2 + 0];
                float v1 = acc[mt][nt][half * 2 + 1];
                float2 o;
                if (MODE) {
                    o.x = lrelu(v0 * s_dv[col] + s_sn[col] * nz + s_bb[col]);
                    o.y = lrelu(v1 * s_dv[col + 1] + s_sn[col + 1] * nz + s_bb[col + 1]);
                    *(float2*)&outp[base + col] = o;
                } else {
                    o.x = v0; o.y = v1;
                    *(float2*)&g_y[base + col] = o;
                }
            }
        }
}

// ---- blur + demod + noise + bias + lrelu, then pre-split *s2*wscale for conv2 --
__global__ void k_blur(const float* __restrict__ noise1, const float* __restrict__ sn1,
                       const float* __restrict__ bias1) {
    int q = blockIdx.x, p = blockIdx.y, b = blockIdx.z;
    int c = threadIdx.x << 2;
    const float fw[4] = {1.f, 3.f, 3.f, 1.f};
    float4 acc = make_float4(0.f, 0.f, 0.f, 0.f);
#pragma unroll
    for (int eh = 0; eh < 4; eh++) {
        int pp = p + eh - 1;
        if ((unsigned)pp >= HOUT) continue;
        float4 row = make_float4(0.f, 0.f, 0.f, 0.f);
#pragma unroll
        for (int ew = 0; ew < 4; ew++) {
            int qq = q + ew - 1;
            if ((unsigned)qq >= WOUT) continue;
            float4 v = *(const float4*)&g_y[(((size_t)b * HOUT + pp) * WOUT + qq) * CH + c];
            row.x += v.x * fw[ew]; row.y += v.y * fw[ew];
            row.z += v.z * fw[ew]; row.w += v.w * fw[ew];
        }
        acc.x += row.x * fw[eh]; acc.y += row.y * fw[eh];
        acc.z += row.z * fw[eh]; acc.w += row.w * fw[eh];
    }
    const float inv16 = 0.0625f;
    float4 dv = *(const float4*)&g_d1[b][c];
    float4 sn = *(const float4*)&sn1[c];
    float4 bb = *(const float4*)&bias1[c];
    float nz = noise1[((size_t)b * HOUT + p) * WOUT + q];
    float o0 = lrelu(acc.x * inv16 * dv.x + sn.x * nz + bb.x);
    float o1 = lrelu(acc.y * inv16 * dv.y + sn.y * nz + bb.y);
    float o2 = lrelu(acc.z * inv16 * dv.z + sn.z * nz + bb.z);
    float o3 = lrelu(acc.w * inv16 * dv.w + sn.w * nz + bb.w);
    float a0 = o0 * (g_s2[b][c] * WSCALE);
    float a1 = o1 * (g_s2[b][c + 1] * WSCALE);
    float a2 = o2 * (g_s2[b][c + 2] * WSCALE);
    float a3 = o3 * (g_s2[b][c + 3] * WSCALE);
    uint32_t h0 = pack_bf16(a0, a1);
    uint32_t h1 = pack_bf16(a2, a3);
    uint32_t lw0 = pack_bf16(a0 - bf_lo(h0), a1 - bf_hi(h0));
    uint32_t lw1 = pack_bf16(a2 - bf_lo(h1), a3 - bf_hi(h1));
    size_t pi = (((size_t)b * HOUT + p) * WOUT + q) * 256 + (c >> 1);
    g_x1h[pi] = h0; g_x1h[pi + 1] = h1;
    g_x1l[pi] = lw0; g_x1l[pi + 1] = lw1;
}

__global__ void k_rgb(const float* __restrict__ x2, const float* __restrict__ wr,
                      const float* __restrict__ br, float* __restrict__ rgb) {
    int b = blockIdx.y, tid = threadIdx.x;
    __shared__ float wc[CH * 3];
    const float wscale = 0.044194173824159216f;
    for (int k = tid; k < CH * 3; k += 256) {
        int ci = k / 3;
        wc[k] = g_sr[b][ci] * wscale * wr[k];
    }
    __syncthreads();
    int warp = tid >> 5, lane = tid & 31;
    int pix = blockIdx.x * 8 + warp;
    const float* xp = x2 + ((size_t)b * HOUT * WOUT + pix) * CH;
    float a0 = 0.f, a1 = 0.f, a2 = 0.f;
    for (int ci = lane; ci < CH; ci += 32) {
        float v = xp[ci];
        a0 = fmaf(v, wc[ci * 3 + 0], a0);
        a1 = fmaf(v, wc[ci * 3 + 1], a1);
        a2 = fmaf(v, wc[ci * 3 + 2], a2);
    }
#pragma unroll
    for (int o = 16; o; o >>= 1) {
        a0 += __shfl_xor_sync(0xffffffffu, a0, o);
        a1 += __shfl_xor_sync(0xffffffffu, a1, o);
        a2 += __shfl_xor_sync(0xffffffffu, a2, o);
    }
    if (lane == 0) {
        size_t base = ((size_t)b * HOUT * WOUT + pix) * 3;
        rgb[base + 0] = lrelu(a0 + br[0]);
        rgb[base + 1] = lrelu(a1 + br[1]);
        rgb[base + 2] = lrelu(a2 + br[2]);
    }
}

extern "C" void kernel_launch(void* const* d_in, const int* in_sizes, int n_in,
                              void* d_out, int out_size) {
    const float* x       = (const float*)d_in[0];
    const float* w       = (const float*)d_in[1];
    const float* noise1  = (const float*)d_in[2];
    const float* noise2  = (const float*)d_in[3];
    const float* fcl1_w  = (const float*)d_in[4];
    const float* fcl1_b  = (const float*)d_in[5];
    const float* conv1_w = (const float*)d_in[6];
    const float* sn1     = (const float*)d_in[7];
    const float* bias1   = (const float*)d_in[8];
    const float* fcl2_w  = (const float*)d_in[9];
    const float* fcl2_b  = (const float*)d_in[10];
    const float* conv2_w = (const float*)d_in[11];
    const float* sn2     = (const float*)d_in[12];
    const float* bias2   = (const float*)d_in[13];
    const float* fclr_w  = (const float*)d_in[14];
    const float* fclr_b  = (const float*)d_in[15];
    const float* convr_w = (const float*)d_in[16];
    const float* biasr   = (const float*)d_in[17];
    float* out = (float*)d_out;
    float* xpart = out;
    float* rgbpart = out + (size_t)BATCH * HOUT * WOUT * CH;

    k_styles<<<dim3(BATCH, 3), 512>>>(w, fcl1_w, fcl1_b, fcl2_w, fcl2_b, fclr_w, fclr_b);
    k_wsq<<<(CH * CH) / 256, 256>>>(conv1_w, conv2_w);
    k_demod<<<dim3(BATCH, 2), 512>>>();
    k_presplit_x<<<16384, 256>>>(x);
    k_wsplit<<<4608, 256>>>(conv1_w, 0);
    k_wsplit<<<4608, 256>>>(conv2_w, 1);

    Taps tee; tee.n = 4;
    tee.t[0] = 0; tee.di[0] = -1; tee.dj[0] = -1;
    tee.t[1] = 2; tee.di[1] = -1; tee.dj[1] = 0;
    tee.t[2] = 6; tee.di[2] = 0;  tee.dj[2] = -1;
    tee.t[3] = 8; tee.di[3] = 0;  tee.dj[3] = 0;
    Taps teo; teo.n = 2;
    teo.t[0] = 1; teo.di[0] = -1; teo.dj[0] = 0;
    teo.t[1] = 7; teo.di[1] = 0;  teo.dj[1] = 0;
    Taps toe; toe.n = 2;
    toe.t[0] = 3; toe.di[0] = 0; toe.dj[0] = -1;
    toe.t[1] = 5; toe.di[1] = 0; toe.dj[1] = 0;
    Taps too; too.n = 1;
    too.t[0] = 4; too.di[0] = 0; too.dj[0] = 0;

    dim3 gT(4, 8, BATCH);
    k_gemm<0><<<gT, 256, GSMEM>>>(tee, 0, 0, nullptr, nullptr, nullptr, nullptr);
    k_gemm<0><<<gT, 256, GSMEM>>>(teo, 0, 1, nullptr, nullptr, nullptr, nullptr);
    k_gemm<0><<<gT, 256, GSMEM>>>(toe, 1, 0, nullptr, nullptr, nullptr, nullptr);
    k_gemm<0><<<gT, 256, GSMEM>>>(too, 1, 1, nullptr, nullptr, nullptr, nullptr);

    k_blur<<<dim3(WOUT, HOUT, BATCH), 128>>>(noise1, sn1, bias1);

    Taps t2; t2.n = 9;
    for (int dh = 0; dh < 3; dh++)
        for (int dw = 0; dw < 3; dw++) {
            int i = dh * 3 + dw;
            t2.t[i] = i; t2.di[i] = dh - 1; t2.dj[i] = dw - 1;
        }
    k_gemm<1><<<dim3(4, 32, BATCH), 256, GSMEM>>>(t2, 0, 0, noise2, sn2, bias2, xpart);

    k_rgb<<<dim3(HOUT * WOUT / 8, BATCH), 256>>>(xpart, convr_w, biasr, rgbpart);
}

// round 11
// speedup vs baseline: 2.7083x; 1.0852x over previous
#include <cuda_runtime.h>
#include <cstdint>

#define BATCH 16
#define HIN 32
#define WIN 32
#define CH 512
#define HOUT 64
#define WOUT 64
#define WSCALE 0.014731391274719742f

__device__ float g_s1[BATCH][CH];
__device__ float g_s2[BATCH][CH];
__device__ float g_sr[BATCH][CH];
__device__ float g_d1[BATCH][CH];
__device__ float g_d2[BATCH][CH];
__device__ float g_wsq1[CH * CH];
__device__ float g_wsq2[CH * CH];
__device__ float g_y[(size_t)BATCH * HOUT * WOUT * CH];
// pre-split bf16 activations (u32 = bf16x2 channel pair), NHWC/2
__device__ uint32_t g_xh[(size_t)BATCH * HIN * WIN * 256];
__device__ uint32_t g_xl[(size_t)BATCH * HIN * WIN * 256];
__device__ uint32_t g_x1h[(size_t)BATCH * HOUT * WOUT * 256];
__device__ uint32_t g_x1l[(size_t)BATCH * HOUT * WOUT * 256];
// pre-split weights in fragment order: [tap][cob4][kci16][blk32][128 u32]
#define WSPN (9 * 4 * 16 * 32 * 128)
__device__ uint32_t g_wspA[WSPN];
__device__ uint32_t g_wspB[WSPN];

__device__ __forceinline__ float lrelu(float v) { return v > 0.f ? v : 0.2f * v; }

__device__ __forceinline__ uint32_t smem_u32(const void* p) {
    uint32_t a;
    asm("{ .reg .u64 t; cvta.to.shared.u64 t, %1; cvt.u32.u64 %0, t; }" : "=r"(a) : "l"(p));
    return a;
}
__device__ __forceinline__ uint32_t pack_bf16(float f0, float f1) {
    uint32_t r;
    asm("cvt.rn.bf16x2.f32 %0, %1, %2;" : "=r"(r) : "f"(f1), "f"(f0));
    return r;
}
__device__ __forceinline__ float bf_lo(uint32_t p) { return __uint_as_float(p << 16); }
__device__ __forceinline__ float bf_hi(uint32_t p) { return __uint_as_float(p & 0xffff0000u); }
__device__ __forceinline__ void mma16(float* d, const uint32_t* a, uint32_t b0, uint32_t b1) {
    asm volatile(
        "mma.sync.aligned.m16n8k16.row.col.f32.bf16.bf16.f32 "
        "{%0,%1,%2,%3},{%4,%5,%6,%7},{%8,%9},{%0,%1,%2,%3};"
        : "+f"(d[0]), "+f"(d[1]), "+f"(d[2]), "+f"(d[3])
        : "r"(a[0]), "r"(a[1]), "r"(a[2]), "r"(a[3]), "r"(b0), "r"(b1));
}
__device__ __forceinline__ void lds128(uint32_t* r, uint32_t a) {
    asm volatile("ld.shared.v4.b32 {%0,%1,%2,%3},[%4];"
                 : "=r"(r[0]), "=r"(r[1]), "=r"(r[2]), "=r"(r[3]) : "r"(a));
}
__device__ __forceinline__ void sts32(uint32_t a, uint32_t v) {
    asm volatile("st.shared.b32 [%0],%1;" :: "r"(a), "r"(v) : "memory");
}
__device__ __forceinline__ void cpa16(uint32_t dst, const uint32_t* src) {
    asm volatile("cp.async.cg.shared.global [%0], [%1], 16;"
                 :: "r"(dst), "l"(src) : "memory");
}
#define CP_COMMIT() asm volatile("cp.async.commit_group;" ::: "memory")
#define CP_WAIT0() asm volatile("cp.async.wait_group 0;" ::: "memory")

// ---------------- styles (3 FC layers), grid (BATCH, 3) -------------------------
__global__ void k_styles(const float* __restrict__ w,
                         const float* __restrict__ f1w, const float* __restrict__ f1b,
                         const float* __restrict__ f2w, const float* __restrict__ f2b,
                         const float* __restrict__ frw, const float* __restrict__ frb) {
    int b = blockIdx.x, which = blockIdx.y, co = threadIdx.x;
    const float* fw = which == 0 ? f1w : (which == 1 ? f2w : frw);
    const float* fb = which == 0 ? f1b : (which == 1 ? f2b : frb);
    __shared__ float sw_[CH];
    sw_[co] = w[b * CH + co];
    __syncthreads();
    float acc = 0.f;
#pragma unroll 4
    for (int ci = 0; ci < CH; ci++) acc = fmaf(sw_[ci], fw[ci * CH + co], acc);
    float v = acc * 0.044194173824159216f + fb[co];
    if (which == 0) g_s1[b][co] = v;
    else if (which == 1) g_s2[b][co] = v;
    else g_sr[b][co] = v;
}

__global__ void k_wsq(const float* __restrict__ w1, const float* __restrict__ w2) {
    int idx = blockIdx.x * 256 + threadIdx.x;
    const float ws2 = 1.0f / 4608.0f;
    float a1 = 0.f, a2 = 0.f;
#pragma unroll
    for (int t = 0; t < 9; t++) {
        float v1 = w1[(size_t)t * CH * CH + idx];
        a1 = fmaf(v1, v1, a1);
        float v2 = w2[(size_t)t * CH * CH + idx];
        a2 = fmaf(v2, v2, a2);
    }
    g_wsq1[idx] = a1 * ws2;
    g_wsq2[idx] = a2 * ws2;
}

__global__ void k_demod() {
    int b = blockIdx.x, which = blockIdx.y, co = threadIdx.x;
    __shared__ float ss[CH];
    float s = which ? g_s2[b][co] : g_s1[b][co];
    ss[co] = s * s;
    __syncthreads();
    const float* wsq = which ? g_wsq2 : g_wsq1;
    float acc = 0.f;
#pragma unroll 4
    for (int ci = 0; ci < CH; ci++) acc = fmaf(ss[ci], wsq[ci * CH + co], acc);
    float d = rsqrtf(acc + 1e-8f);
    if (which) g_d2[b][co] = d;
    else g_d1[b][co] = d;
}

// ---------------- weight pre-split into fragment order, grid 4608 ---------------
__global__ void k_wsplit(const float* __restrict__ cw, int which) {
    uint32_t* __restrict__ out = which ? g_wspB : g_wspA;
    int bx = blockIdx.x;
    int u = bx >> 3, part = bx & 7;
    int tap = u >> 6, r = u & 63, cob = r >> 4, kci = r & 15;
    int within = part * 256 + threadIdx.x;
    int blk = within >> 6, s = within & 63, lane = s >> 1, br = s & 1;
    int n = (blk & 15) * 8 + (lane >> 2);
    int kc = blk >> 4;
    int kk = kc * 16 + ((lane & 3) << 1) + (br << 3);
    int ci = kci * 32 + kk, co = cob * 128 + n;
    float w0 = cw[((size_t)tap * CH + ci) * CH + co];
    float w1 = cw[((size_t)tap * CH + ci + 1) * CH + co];
    uint32_t h = pack_bf16(w0, w1);
    uint32_t l = pack_bf16(w0 - bf_lo(h), w1 - bf_hi(h));
    size_t base = ((((size_t)tap * 4 + cob) * 16 + kci) * 32 + blk) * 128 + lane * 4 + br;
    out[base] = h;
    out[base + 2] = l;
}

// ---------------- pre-split x * s1 * wscale, grid 16384 -------------------------
__global__ void k_presplit_x(const float* __restrict__ x) {
    int id = blockIdx.x * 256 + threadIdx.x;
    int p2 = id & 255;
    int pix = id >> 8;
    int b = pix >> 10;
    int ci = p2 * 2;
    float v0 = x[(size_t)pix * CH + ci] * (g_s1[b][ci] * WSCALE);
    float v1 = x[(size_t)pix * CH + ci + 1] * (g_s1[b][ci + 1] * WSCALE);
    uint32_t h = pack_bf16(v0, v1);
    g_xh[id] = h;
    g_xl[id] = pack_bf16(v0 - bf_lo(h), v1 - bf_hi(h));
}

struct Taps { int n; int t[9]; int di[9]; int dj[9]; };
struct Taps4 { Taps c[4]; };

// Implicit-GEMM conv, bf16 3-term split, 2-stage pipelined (double-buffered A+B).
// MODE 0: 4 convT parity classes in ONE launch (blockIdx.y: cls=y>>3, tile=y&7).
// MODE 1: conv2 3x3 + fused epilogue.
#define BLK 132
#define SBU ((16 + 16 + 32) * BLK)      // u32 per stage
#define SBB (SBU * 4)                   // bytes per stage
#define GSMEM (2 * SBB)

template <int MODE>
__global__ __launch_bounds__(256, 2) void k_gemm(
    Taps4 t4, const float* __restrict__ noise, const float* __restrict__ snp,
    const float* __restrict__ biasp, float* __restrict__ outp) {
    constexpr int HI = MODE ? HOUT : HIN;
    constexpr int WI = MODE ? WOUT : WIN;
    extern __shared__ uint32_t smu[];
    __shared__ float s_dv[128], s_sn[128], s_bb[128];

    const int tid = threadIdx.x, lane = tid & 31, wid = tid >> 5;
    const int wm = wid & 3, wn = wid >> 2;
    const int b = blockIdx.z, co0 = blockIdx.x * 128;
    int pb, qb, cls = 0;
    if (MODE) { pb = (blockIdx.y >> 2) * 8; qb = (blockIdx.y & 3) * 16; }
    else {
        cls = blockIdx.y >> 3;
        int yt = blockIdx.y & 7;
        pb = (yt >> 1) * 8; qb = (yt & 1) * 16;
    }
    const Taps& taps = t4.c[MODE ? 0 : cls];
    const int uo = cls >> 1, vo = cls & 1;

    const uint32_t* axh = MODE ? g_x1h : g_xh;
    const uint32_t* axl = MODE ? g_x1l : g_xl;
    const uint32_t* wsp = MODE ? g_wspB : g_wspA;

    if (MODE && tid < 128) {
        s_dv[tid] = g_d2[b][co0 + tid];
        s_sn[tid] = snp[co0 + tid];
        s_bb[tid] = biasp[co0 + tid];
    }

    const uint32_t S0 = smem_u32(smu);
    const uint32_t AHr = 0, ALr = 16 * BLK * 4, BHr = 32 * BLK * 4;

    // A staging coords
    const int arow = tid >> 1, akhalf8 = (tid & 1) * 8;
    const int arg = arow >> 4, ar8 = (arow >> 3) & 1, alb = (arow & 7) << 2;
    const int apr = arow >> 4, apc = arow & 15;
    const uint32_t arel = (uint32_t)(((tid & 1) * 8 + arg) * BLK) * 4;

    float acc[2][8][4];
#pragma unroll
    for (int i = 0; i < 2; i++)
#pragma unroll
        for (int j = 0; j < 8; j++)
#pragma unroll
            for (int k = 0; k < 4; k++) acc[i][j][k] = 0.f;

    const int nkb = taps.n * 16;

    // ---- helpers as lambdas
    auto stageB = [&](int kb, uint32_t off) {
        const int tp = kb >> 4, kci = kb & 15;
        const uint32_t* wb =
            wsp + ((((size_t)taps.t[tp] * 4 + blockIdx.x) * 16 + kci) * 32) * 128;
#pragma unroll
        for (int c = 0; c < 4; c++) {
            int l16 = tid + c * 256;
            int blk = l16 >> 5, in16 = l16 & 31;
            cpa16(S0 + off + BHr + (uint32_t)(blk * (BLK * 4) + in16 * 16),
                  wb + blk * 128 + in16 * 4);
        }
        CP_COMMIT();
    };
    auto loadA = [&](int kb, uint4* hv, uint4* lv) {
        const int tp = kb >> 4, kci = kb & 15;
        int gp = pb + apr + taps.di[tp], gq = qb + apc + taps.dj[tp];
        if ((unsigned)gp < (unsigned)HI && (unsigned)gq < (unsigned)WI) {
            size_t o = ((size_t)(b * HI + gp) * WI + gq) * 256 + kci * 16 + akhalf8;
            hv[0] = *(const uint4*)(axh + o);
            hv[1] = *(const uint4*)(axh + o + 4);
            lv[0] = *(const uint4*)(axl + o);
            lv[1] = *(const uint4*)(axl + o + 4);
        } else {
            hv[0] = hv[1] = lv[0] = lv[1] = make_uint4(0u, 0u, 0u, 0u);
        }
    };
    auto storeA = [&](uint32_t off, const uint4* hv, const uint4* lv) {
        uint32_t ab = S0 + off + AHr + arel, abL = S0 + off + ALr + arel;
#define APUT(J, HV, LV)                                                              \
    {                                                                                \
        uint32_t off_ = (((alb | ((J) & 3)) << 2) + (ar8 | (((J) >> 2) << 1))) << 2; \
        sts32(ab + off_, (HV));                                                      \
        sts32(abL + off_, (LV));                                                     \
    }
        APUT(0, hv[0].x, lv[0].x) APUT(1, hv[0].y, lv[0].y)
        APUT(2, hv[0].z, lv[0].z) APUT(3, hv[0].w, lv[0].w)
        APUT(4, hv[1].x, lv[1].x) APUT(5, hv[1].y, lv[1].y)
        APUT(6, hv[1].z, lv[1].z) APUT(7, hv[1].w, lv[1].w)
#undef APUT
    };

    // ---- prologue: stage kb=0 into buf0
    {
        stageB(0, 0);
        uint4 hv[2], lv[2];
        loadA(0, hv, lv);
        storeA(0, hv, lv);
    }

    for (int kb = 0; kb < nkb; kb++) {
        const uint32_t off = (kb & 1) ? SBB : 0;
        const uint32_t offn = (kb & 1) ? 0 : SBB;
        CP_WAIT0();
        __syncthreads();
        const bool hasnext = (kb + 1 < nkb);
        uint4 hv[2], lv[2];
        if (hasnext) {
            stageB(kb + 1, offn);   // LDGSTS runs under the MMAs below
            loadA(kb + 1, hv, lv);  // LDG latency hidden under the MMAs
        }
        // ---- MMA over staged 32-k block
#pragma unroll
        for (int kc = 0; kc < 2; kc++) {
            uint32_t ah[2][4], al[2][4];
#pragma unroll
            for (int mt = 0; mt < 2; mt++) {
                uint32_t ba = (uint32_t)((kc * 8 + (wm << 1) + mt) * BLK) * 4 + lane * 16;
                lds128(ah[mt], S0 + off + AHr + ba);
                lds128(al[mt], S0 + off + ALr + ba);
            }
#pragma unroll
            for (int nt = 0; nt < 8; nt++) {
                uint32_t bbf[4];
                lds128(bbf, S0 + off + BHr +
                                (uint32_t)((kc * 16 + (wn << 3) + nt) * BLK) * 4 + lane * 16);
#pragma unroll
                for (int mt = 0; mt < 2; mt++) {
                    mma16(acc[mt][nt], ah[mt], bbf[0], bbf[1]);
                    mma16(acc[mt][nt], ah[mt], bbf[2], bbf[3]);
                    mma16(acc[mt][nt], al[mt], bbf[0], bbf[1]);
                }
            }
        }
        if (hasnext) storeA(offn, hv, lv);
        __syncthreads();
    }

    // ---- epilogue
    const int r0 = wm * 32 + (lane >> 2);
    const int cb = wn * 64 + (lane & 3) * 2;
#pragma unroll
    for (int mt = 0; mt < 2; mt++)
#pragma unroll
        for (int half = 0; half < 2; half++) {
            int m = r0 + mt * 16 + half * 8;
            int pr = m >> 4, pc = m & 15;
            int p, q;
            if (MODE) { p = pb + pr; q = qb + pc; }
            else      { p = 2 * (pb + pr) + uo; q = 2 * (qb + pc) + vo; }
            size_t base = (((size_t)b * HOUT + p) * WOUT + q) * CH + co0;
            float nz = MODE ? noise[((size_t)b * HOUT + p) * WOUT + q] : 0.f;
#pragma unroll
            for (int nt = 0; nt < 8; nt++) {
                int col = cb + nt * 8;
                float v0 = acc[mt][nt][half * 2 + 0];
                float v1 = acc[mt][nt][half * 2 + 1];
                float2 o;
                if (MODE) {
                    o.x = lrelu(v0 * s_dv[col] + s_sn[col] * nz + s_bb[col]);
                    o.y = lrelu(v1 * s_dv[col + 1] + s_sn[col + 1] * nz + s_bb[col + 1]);
                    *(float2*)&outp[base + col] = o;
                } else {
                    o.x = v0; o.y = v1;
                    *(float2*)&g_y[base + col] = o;
                }
            }
        }
}

// ---- blur + demod + noise + bias + lrelu, then pre-split *s2*wscale for conv2 --
__global__ void k_blur(const float* __restrict__ noise1, const float* __restrict__ sn1,
                       const float* __restrict__ bias1) {
    int q = blockIdx.x, p = blockIdx.y, b = blockIdx.z;
    int c = threadIdx.x << 2;
    const float fw[4] = {1.f, 3.f, 3.f, 1.f};
    float4 acc = make_float4(0.f, 0.f, 0.f, 0.f);
#pragma unroll
    for (int eh = 0; eh < 4; eh++) {
        int pp = p + eh - 1;
        if ((unsigned)pp >= HOUT) continue;
        float4 row = make_float4(0.f, 0.f, 0.f, 0.f);
#pragma unroll
        for (int ew = 0; ew < 4; ew++) {
            int qq = q + ew - 1;
            if ((unsigned)qq >= WOUT) continue;
            float4 v = *(const float4*)&g_y[(((size_t)b * HOUT + pp) * WOUT + qq) * CH + c];
            row.x += v.x * fw[ew]; row.y += v.y * fw[ew];
            row.z += v.z * fw[ew]; row.w += v.w * fw[ew];
        }
        acc.x += row.x * fw[eh]; acc.y += row.y * fw[eh];
        acc.z += row.z * fw[eh]; acc.w += row.w * fw[eh];
    }
    const float inv16 = 0.0625f;
    float4 dv = *(const float4*)&g_d1[b][c];
    float4 sn = *(const float4*)&sn1[c];
    float4 bb = *(const float4*)&bias1[c];
    float nz = noise1[((size_t)b * HOUT + p) * WOUT + q];
    float o0 = lrelu(acc.x * inv16 * dv.x + sn.x * nz + bb.x);
    float o1 = lrelu(acc.y * inv16 * dv.y + sn.y * nz + bb.y);
    float o2 = lrelu(acc.z * inv16 * dv.z + sn.z * nz + bb.z);
    float o3 = lrelu(acc.w * inv16 * dv.w + sn.w * nz + bb.w);
    float a0 = o0 * (g_s2[b][c] * WSCALE);
    float a1 = o1 * (g_s2[b][c + 1] * WSCALE);
    float a2 = o2 * (g_s2[b][c + 2] * WSCALE);
    float a3 = o3 * (g_s2[b][c + 3] * WSCALE);
    uint32_t h0 = pack_bf16(a0, a1);
    uint32_t h1 = pack_bf16(a2, a3);
    uint32_t lw0 = pack_bf16(a0 - bf_lo(h0), a1 - bf_hi(h0));
    uint32_t lw1 = pack_bf16(a2 - bf_lo(h1), a3 - bf_hi(h1));
    size_t pi = (((size_t)b * HOUT + p) * WOUT + q) * 256 + (c >> 1);
    g_x1h[pi] = h0; g_x1h[pi + 1] = h1;
    g_x1l[pi] = lw0; g_x1l[pi + 1] = lw1;
}

__global__ void k_rgb(const float* __restrict__ x2, const float* __restrict__ wr,
                      const float* __restrict__ br, float* __restrict__ rgb) {
    int b = blockIdx.y, tid = threadIdx.x;
    __shared__ float wc[CH * 3];
    const float wscale = 0.044194173824159216f;
    for (int k = tid; k < CH * 3; k += 256) {
        int ci = k / 3;
        wc[k] = g_sr[b][ci] * wscale * wr[k];
    }
    __syncthreads();
    int warp = tid >> 5, lane = tid & 31;
    int pix = blockIdx.x * 8 + warp;
    const float* xp = x2 + ((size_t)b * HOUT * WOUT + pix) * CH;
    float a0 = 0.f, a1 = 0.f, a2 = 0.f;
    for (int ci = lane; ci < CH; ci += 32) {
        float v = xp[ci];
        a0 = fmaf(v, wc[ci * 3 + 0], a0);
        a1 = fmaf(v, wc[ci * 3 + 1], a1);
        a2 = fmaf(v, wc[ci * 3 + 2], a2);
    }
#pragma unroll
    for (int o = 16; o; o >>= 1) {
        a0 += __shfl_xor_sync(0xffffffffu, a0, o);
        a1 += __shfl_xor_sync(0xffffffffu, a1, o);
        a2 += __shfl_xor_sync(0xffffffffu, a2, o);
    }
    if (lane == 0) {
        size_t base = ((size_t)b * HOUT * WOUT + pix) * 3;
        rgb[base + 0] = lrelu(a0 + br[0]);
        rgb[base + 1] = lrelu(a1 + br[1]);
        rgb[base + 2] = lrelu(a2 + br[2]);
    }
}

extern "C" void kernel_launch(void* const* d_in, const int* in_sizes, int n_in,
                              void* d_out, int out_size) {
    const float* x       = (const float*)d_in[0];
    const float* w       = (const float*)d_in[1];
    const float* noise1  = (const float*)d_in[2];
    const float* noise2  = (const float*)d_in[3];
    const float* fcl1_w  = (const float*)d_in[4];
    const float* fcl1_b  = (const float*)d_in[5];
    const float* conv1_w = (const float*)d_in[6];
    const float* sn1     = (const float*)d_in[7];
    const float* bias1   = (const float*)d_in[8];
    const float* fcl2_w  = (const float*)d_in[9];
    const float* fcl2_b  = (const float*)d_in[10];
    const float* conv2_w = (const float*)d_in[11];
    const float* sn2     = (const float*)d_in[12];
    const float* bias2   = (const float*)d_in[13];
    const float* fclr_w  = (const float*)d_in[14];
    const float* fclr_b  = (const float*)d_in[15];
    const float* convr_w = (const float*)d_in[16];
    const float* biasr   = (const float*)d_in[17];
    float* out = (float*)d_out;
    float* xpart = out;
    float* rgbpart = out + (size_t)BATCH * HOUT * WOUT * CH;

    cudaFuncSetAttribute(k_gemm<0>, cudaFuncAttributeMaxDynamicSharedMemorySize, GSMEM);
    cudaFuncSetAttribute(k_gemm<1>, cudaFuncAttributeMaxDynamicSharedMemorySize, GSMEM);

    k_styles<<<dim3(BATCH, 3), 512>>>(w, fcl1_w, fcl1_b, fcl2_w, fcl2_b, fclr_w, fclr_b);
    k_wsq<<<(CH * CH) / 256, 256>>>(conv1_w, conv2_w);
    k_demod<<<dim3(BATCH, 2), 512>>>();
    k_presplit_x<<<16384, 256>>>(x);
    k_wsplit<<<4608, 256>>>(conv1_w, 0);
    k_wsplit<<<4608, 256>>>(conv2_w, 1);

    // convT parity classes: y[2i+u,2j+v] = sum_t w[t]*x[i+di, j+dj]
    Taps4 tc{};
    tc.c[0].n = 4;  // ee
    tc.c[0].t[0] = 0; tc.c[0].di[0] = -1; tc.c[0].dj[0] = -1;
    tc.c[0].t[1] = 2; tc.c[0].di[1] = -1; tc.c[0].dj[1] = 0;
    tc.c[0].t[2] = 6; tc.c[0].di[2] = 0;  tc.c[0].dj[2] = -1;
    tc.c[0].t[3] = 8; tc.c[0].di[3] = 0;  tc.c[0].dj[3] = 0;
    tc.c[1].n = 2;  // eo
    tc.c[1].t[0] = 1; tc.c[1].di[0] = -1; tc.c[1].dj[0] = 0;
    tc.c[1].t[1] = 7; tc.c[1].di[1] = 0;  tc.c[1].dj[1] = 0;
    tc.c[2].n = 2;  // oe
    tc.c[2].t[0] = 3; tc.c[2].di[0] = 0; tc.c[2].dj[0] = -1;
    tc.c[2].t[1] = 5; tc.c[2].di[1] = 0; tc.c[2].dj[1] = 0;
    tc.c[3].n = 1;  // oo
    tc.c[3].t[0] = 4; tc.c[3].di[0] = 0; tc.c[3].dj[0] = 0;

    k_gemm<0><<<dim3(4, 32, BATCH), 256, GSMEM>>>(tc, nullptr, nullptr, nullptr, nullptr);

    k_blur<<<dim3(WOUT, HOUT, BATCH), 128>>>(noise1, sn1, bias1);

    Taps4 t2{};
    t2.c[0].n = 9;
    for (int dh = 0; dh < 3; dh++)
        for (int dw = 0; dw < 3; dw++) {
            int i = dh * 3 + dw;
            t2.c[0].t[i] = i; t2.c[0].di[i] = dh - 1; t2.c[0].dj[i] = dw - 1;
        }
    k_gemm<1><<<dim3(4, 32, BATCH), 256, GSMEM>>>(t2, noise2, sn2, bias2, xpart);

    k_rgb<<<dim3(HOUT * WOUT / 8, BATCH), 256>>>(xpart, convr_w, biasr, rgbpart);
}